// round 3
// baseline (speedup 1.0000x reference)
#include <cuda_runtime.h>

// ---------------- problem constants ----------------
#define N_PAPER  100000
#define N_AUTHOR 100000
#define N_FIELD  50000
#define F_IN 128
#define HID  64
#define OUTF 349
#define E_WR 1000000
#define E_RW 1000000
#define E_CI 2000000
#define E_HT 1000000
#define E_RH 1000000

// ---------------- scratch (static device memory; no allocs) ----------------
// projected source features (layer 1)
__device__ float g_h_wr[N_AUTHOR * HID];   // author @ wl1_wr
__device__ float g_h_rw[N_PAPER  * HID];   // paper  @ wl1_rw
__device__ float g_h_ci[N_PAPER  * HID];   // paper  @ wl1_ci
__device__ float g_h_ht[N_PAPER  * HID];   // paper  @ wl1_ht
__device__ float g_h_rh[N_FIELD  * HID];   // field  @ wl1_rh

// layer-1 node outputs (self-term GEMM writes here, finalize adds agg + relu)
__device__ float g_p1[N_PAPER  * HID];
__device__ float g_a1[N_AUTHOR * HID];
__device__ float g_f1[N_FIELD  * HID];

// summed weights / biases
__device__ float g_wsum1p[F_IN * HID];
__device__ float g_bsum1p[HID];
__device__ float g_wsum2[HID * OUTF];
__device__ float g_bsum2[OUTF];

// one contiguous accumulator region so a single zero-kernel clears it
// layout (floats):
#define OFF_ACC_P_WR 0
#define OFF_ACC_P_CI (OFF_ACC_P_WR + N_PAPER * HID)     // 6,400,000
#define OFF_ACC_P_RH (OFF_ACC_P_CI + N_PAPER * HID)     // 12,800,000
#define OFF_ACC_A    (OFF_ACC_P_RH + N_PAPER * HID)     // 19,200,000
#define OFF_ACC_F    (OFF_ACC_A    + N_AUTHOR * HID)    // 25,600,000
#define OFF_CNT_WR   (OFF_ACC_F    + N_FIELD * HID)     // 28,800,000 (dst=paper)
#define OFF_CNT_CI   (OFF_CNT_WR   + N_PAPER)           // (dst=paper)
#define OFF_CNT_RH   (OFF_CNT_CI   + N_PAPER)           // (dst=paper)
#define OFF_CNT_RW   (OFF_CNT_RH   + N_PAPER)           // (dst=author)
#define OFF_CNT_HT   (OFF_CNT_RW   + N_AUTHOR)          // (dst=field)
#define OFF_ACC2_WR  (OFF_CNT_HT   + N_FIELD)           // 29,250,000
#define OFF_ACC2_CI  (OFF_ACC2_WR  + N_PAPER * HID)
#define OFF_ACC2_RH  (OFF_ACC2_CI  + N_PAPER * HID)
#define ACC_TOTAL    (OFF_ACC2_RH  + N_PAPER * HID)     // 48,450,000 floats
__device__ float g_acc[ACC_TOTAL];

// ---------------- kernels ----------------

__global__ void zero_kernel(float4* __restrict__ p, int n4) {
    int idx = blockIdx.x * blockDim.x + threadIdx.x;
    if (idx < n4) p[idx] = make_float4(0.f, 0.f, 0.f, 0.f);
}

// out = w0 + w1 + w2 elementwise
__global__ void wsum3_kernel(const float* __restrict__ w0, const float* __restrict__ w1,
                             const float* __restrict__ w2, float* __restrict__ out, int n) {
    int idx = blockIdx.x * blockDim.x + threadIdx.x;
    if (idx < n) out[idx] = w0[idx] + w1[idx] + w2[idx];
}

// C[M x 64] = A[M x 128] @ W[128 x 64] (+ bias if non-null)
// block = 256 threads (16x16), BM=64, BN=64, BK=64 (two chunks)
__global__ void gemm_proj(const float* __restrict__ A, const float* __restrict__ W,
                          const float* __restrict__ bias, float* __restrict__ C, int M) {
    __shared__ float As[64][65];
    __shared__ float Ws[64][64];
    const int row0 = blockIdx.x * 64;
    const int tx = threadIdx.x & 15;
    const int ty = threadIdx.x >> 4;
    float acc[4][4] = {};

    for (int kk = 0; kk < F_IN; kk += 64) {
        for (int i = threadIdx.x; i < 64 * 64; i += 256) {
            int r = i >> 6, k = i & 63;
            int row = row0 + r;
            As[r][k] = (row < M) ? A[row * F_IN + kk + k] : 0.f;
        }
        for (int i = threadIdx.x; i < 64 * 64; i += 256) {
            int k = i >> 6, c = i & 63;
            Ws[k][c] = W[(kk + k) * HID + c];
        }
        __syncthreads();
        #pragma unroll
        for (int k = 0; k < 64; k++) {
            float a0 = As[ty * 4 + 0][k];
            float a1 = As[ty * 4 + 1][k];
            float a2 = As[ty * 4 + 2][k];
            float a3 = As[ty * 4 + 3][k];
            float4 b = *(const float4*)&Ws[k][tx * 4];
            acc[0][0] += a0 * b.x; acc[0][1] += a0 * b.y; acc[0][2] += a0 * b.z; acc[0][3] += a0 * b.w;
            acc[1][0] += a1 * b.x; acc[1][1] += a1 * b.y; acc[1][2] += a1 * b.z; acc[1][3] += a1 * b.w;
            acc[2][0] += a2 * b.x; acc[2][1] += a2 * b.y; acc[2][2] += a2 * b.z; acc[2][3] += a2 * b.w;
            acc[3][0] += a3 * b.x; acc[3][1] += a3 * b.y; acc[3][2] += a3 * b.z; acc[3][3] += a3 * b.w;
        }
        __syncthreads();
    }

    float4 bv = make_float4(0.f, 0.f, 0.f, 0.f);
    if (bias) bv = *(const float4*)&bias[tx * 4];
    #pragma unroll
    for (int r = 0; r < 4; r++) {
        int row = row0 + ty * 4 + r;
        if (row < M) {
            float4 o = make_float4(acc[r][0] + bv.x, acc[r][1] + bv.y,
                                   acc[r][2] + bv.z, acc[r][3] + bv.w);
            *(float4*)&C[row * HID + tx * 4] = o;
        }
    }
}

// degree count: cnt[dst[e]] += 1
__global__ void count_kernel(const int* __restrict__ dst, float* __restrict__ cnt, int E) {
    int idx = blockIdx.x * blockDim.x + threadIdx.x;
    if (idx < E) atomicAdd(&cnt[dst[idx]], 1.0f);
}

// scatter-add 64-dim features: acc[dst[e]] += h[src[e]], float4-vectorized (16 chunks/edge)
__global__ void scatter64(const float4* __restrict__ h, const int* __restrict__ ei, int E,
                          float4* __restrict__ acc) {
    const int* src = ei;
    const int* dst = ei + E;
    int n = E * 16;
    int idx = blockIdx.x * blockDim.x + threadIdx.x;
    if (idx < n) {
        int e = idx >> 4, c = idx & 15;
        int s = __ldg(&src[e]);
        int d = __ldg(&dst[e]);
        float4 v = h[s * 16 + c];
        atomicAdd(&acc[d * 16 + c], v);   // sm_90+ vector red
    }
}

// p1 = relu(p1 + acc0/max(c0,1) + acc1/max(c1,1) + acc2/max(c2,1))
__global__ void fin_paper(float* __restrict__ p,
                          const float* __restrict__ a0, const float* __restrict__ a1,
                          const float* __restrict__ a2,
                          const float* __restrict__ c0, const float* __restrict__ c1,
                          const float* __restrict__ c2, int N) {
    int idx = blockIdx.x * blockDim.x + threadIdx.x;
    if (idx < N * HID) {
        int row = idx >> 6;
        float r0 = 1.0f / fmaxf(c0[row], 1.0f);
        float r1 = 1.0f / fmaxf(c1[row], 1.0f);
        float r2 = 1.0f / fmaxf(c2[row], 1.0f);
        float v = p[idx] + a0[idx] * r0 + a1[idx] * r1 + a2[idx] * r2;
        p[idx] = fmaxf(v, 0.0f);
    }
}

// y = relu(y + acc/max(c,1))
__global__ void fin_one(float* __restrict__ y, const float* __restrict__ a,
                        const float* __restrict__ c, int N) {
    int idx = blockIdx.x * blockDim.x + threadIdx.x;
    if (idx < N * HID) {
        int row = idx >> 6;
        float r = 1.0f / fmaxf(c[row], 1.0f);
        y[idx] = fmaxf(y[idx] + a[idx] * r, 0.0f);
    }
}

// C[M x 349] = sum_t Ahat_t[M x 64] @ W_t[64 x 349] + bias
//   t<3: Ahat_t = A_t / max(cnt_t,1) (mean);  t=3: Ahat = A_3 (self, p1)
__global__ void gemm_out(const float* __restrict__ A0, const float* __restrict__ A1,
                         const float* __restrict__ A2, const float* __restrict__ A3,
                         const float* __restrict__ W0, const float* __restrict__ W1,
                         const float* __restrict__ W2, const float* __restrict__ W3,
                         const float* __restrict__ c0, const float* __restrict__ c1,
                         const float* __restrict__ c2,
                         const float* __restrict__ bias, float* __restrict__ C, int M) {
    __shared__ float As[64][65];
    __shared__ float Ws[64][64];
    const int row0 = blockIdx.x * 64;
    const int col0 = blockIdx.y * 64;
    const int tx = threadIdx.x & 15;
    const int ty = threadIdx.x >> 4;
    float acc[4][4] = {};

    const float* Aps[4] = {A0, A1, A2, A3};
    const float* Wps[4] = {W0, W1, W2, W3};
    const float* cps[4] = {c0, c1, c2, nullptr};

    #pragma unroll
    for (int t = 0; t < 4; t++) {
        const float* A = Aps[t];
        const float* W = Wps[t];
        const float* cp = cps[t];
        for (int i = threadIdx.x; i < 64 * 64; i += 256) {
            int r = i >> 6, k = i & 63;
            int row = row0 + r;
            float v = 0.f;
            if (row < M) {
                v = A[row * HID + k];
                if (cp) v *= 1.0f / fmaxf(cp[row], 1.0f);
            }
            As[r][k] = v;
        }
        for (int i = threadIdx.x; i < 64 * 64; i += 256) {
            int k = i >> 6, c = i & 63;
            int col = col0 + c;
            Ws[k][c] = (col < OUTF) ? W[k * OUTF + col] : 0.f;
        }
        __syncthreads();
        #pragma unroll
        for (int k = 0; k < 64; k++) {
            float a0 = As[ty * 4 + 0][k];
            float a1 = As[ty * 4 + 1][k];
            float a2 = As[ty * 4 + 2][k];
            float a3 = As[ty * 4 + 3][k];
            float4 b = *(const float4*)&Ws[k][tx * 4];
            acc[0][0] += a0 * b.x; acc[0][1] += a0 * b.y; acc[0][2] += a0 * b.z; acc[0][3] += a0 * b.w;
            acc[1][0] += a1 * b.x; acc[1][1] += a1 * b.y; acc[1][2] += a1 * b.z; acc[1][3] += a1 * b.w;
            acc[2][0] += a2 * b.x; acc[2][1] += a2 * b.y; acc[2][2] += a2 * b.z; acc[2][3] += a2 * b.w;
            acc[3][0] += a3 * b.x; acc[3][1] += a3 * b.y; acc[3][2] += a3 * b.z; acc[3][3] += a3 * b.w;
        }
        __syncthreads();
    }

    #pragma unroll
    for (int r = 0; r < 4; r++) {
        int row = row0 + ty * 4 + r;
        if (row >= M) continue;
        #pragma unroll
        for (int c = 0; c < 4; c++) {
            int col = col0 + tx * 4 + c;
            if (col < OUTF) C[row * OUTF + col] = acc[r][c] + bias[col];
        }
    }
}

// ---------------- host launcher ----------------
extern "C" void kernel_launch(void* const* d_in, const int* in_sizes, int n_in,
                              void* d_out, int out_size) {
    (void)in_sizes; (void)n_in; (void)out_size;
    // inputs per metadata order
    const float* x_paper  = (const float*)d_in[0];
    const float* x_author = (const float*)d_in[1];
    const float* x_field  = (const float*)d_in[2];
    const int* ei_wr = (const int*)d_in[3];
    const int* ei_rw = (const int*)d_in[4];
    const int* ei_ci = (const int*)d_in[5];
    const int* ei_ht = (const int*)d_in[6];
    const int* ei_rh = (const int*)d_in[7];
    // layer-1 weights: (wl, wr, b) per edge type in ETS order starting at 8
    const float* wl1_wr = (const float*)d_in[8];
    const float* wr1_wr = (const float*)d_in[9];
    const float* b1_wr  = (const float*)d_in[10];
    const float* wl1_rw = (const float*)d_in[11];
    const float* wr1_rw = (const float*)d_in[12];
    const float* b1_rw  = (const float*)d_in[13];
    const float* wl1_ci = (const float*)d_in[14];
    const float* wr1_ci = (const float*)d_in[15];
    const float* b1_ci  = (const float*)d_in[16];
    const float* wl1_ht = (const float*)d_in[17];
    const float* wr1_ht = (const float*)d_in[18];
    const float* b1_ht  = (const float*)d_in[19];
    const float* wl1_rh = (const float*)d_in[20];
    const float* wr1_rh = (const float*)d_in[21];
    const float* b1_rh  = (const float*)d_in[22];
    // layer-2 weights
    const float* wl2_wr = (const float*)d_in[23];
    const float* wr2_wr = (const float*)d_in[24];
    const float* b2_wr  = (const float*)d_in[25];
    const float* wl2_ci = (const float*)d_in[26];
    const float* wr2_ci = (const float*)d_in[27];
    const float* b2_ci  = (const float*)d_in[28];
    const float* wl2_rh = (const float*)d_in[29];
    const float* wr2_rh = (const float*)d_in[30];
    const float* b2_rh  = (const float*)d_in[31];
    float* out = (float*)d_out;

    // scratch pointers
    float *h_wr, *h_rw, *h_ci, *h_ht, *h_rh, *p1, *a1, *f1;
    float *wsum1p, *bsum1p, *wsum2, *bsum2, *accb;
    cudaGetSymbolAddress((void**)&h_wr, g_h_wr);
    cudaGetSymbolAddress((void**)&h_rw, g_h_rw);
    cudaGetSymbolAddress((void**)&h_ci, g_h_ci);
    cudaGetSymbolAddress((void**)&h_ht, g_h_ht);
    cudaGetSymbolAddress((void**)&h_rh, g_h_rh);
    cudaGetSymbolAddress((void**)&p1, g_p1);
    cudaGetSymbolAddress((void**)&a1, g_a1);
    cudaGetSymbolAddress((void**)&f1, g_f1);
    cudaGetSymbolAddress((void**)&wsum1p, g_wsum1p);
    cudaGetSymbolAddress((void**)&bsum1p, g_bsum1p);
    cudaGetSymbolAddress((void**)&wsum2, g_wsum2);
    cudaGetSymbolAddress((void**)&bsum2, g_bsum2);
    cudaGetSymbolAddress((void**)&accb, g_acc);

    float* acc_p_wr = accb + OFF_ACC_P_WR;
    float* acc_p_ci = accb + OFF_ACC_P_CI;
    float* acc_p_rh = accb + OFF_ACC_P_RH;
    float* acc_a    = accb + OFF_ACC_A;
    float* acc_f    = accb + OFF_ACC_F;
    float* cnt_wr   = accb + OFF_CNT_WR;
    float* cnt_ci   = accb + OFF_CNT_CI;
    float* cnt_rh   = accb + OFF_CNT_RH;
    float* cnt_rw   = accb + OFF_CNT_RW;
    float* cnt_ht   = accb + OFF_CNT_HT;
    float* acc2_wr  = accb + OFF_ACC2_WR;
    float* acc2_ci  = accb + OFF_ACC2_CI;
    float* acc2_rh  = accb + OFF_ACC2_RH;

    const int TPB = 256;

    // 1) zero all accumulators + counts
    {
        int n4 = ACC_TOTAL / 4;
        zero_kernel<<<(n4 + TPB - 1) / TPB, TPB>>>((float4*)accb, n4);
    }

    // 2) summed self-weights/biases
    wsum3_kernel<<<(F_IN * HID + TPB - 1) / TPB, TPB>>>(wr1_wr, wr1_ci, wr1_rh, wsum1p, F_IN * HID);
    wsum3_kernel<<<1, TPB>>>(b1_wr, b1_ci, b1_rh, bsum1p, HID);
    wsum3_kernel<<<(HID * OUTF + TPB - 1) / TPB, TPB>>>(wr2_wr, wr2_ci, wr2_rh, wsum2, HID * OUTF);
    wsum3_kernel<<<(OUTF + TPB - 1) / TPB, TPB>>>(b2_wr, b2_ci, b2_rh, bsum2, OUTF);

    // 3) layer-1 source projections (lin_l)
    gemm_proj<<<(N_AUTHOR + 63) / 64, TPB>>>(x_author, wl1_wr, nullptr, h_wr, N_AUTHOR);
    gemm_proj<<<(N_PAPER  + 63) / 64, TPB>>>(x_paper,  wl1_rw, nullptr, h_rw, N_PAPER);
    gemm_proj<<<(N_PAPER  + 63) / 64, TPB>>>(x_paper,  wl1_ci, nullptr, h_ci, N_PAPER);
    gemm_proj<<<(N_PAPER  + 63) / 64, TPB>>>(x_paper,  wl1_ht, nullptr, h_ht, N_PAPER);
    gemm_proj<<<(N_FIELD  + 63) / 64, TPB>>>(x_field,  wl1_rh, nullptr, h_rh, N_FIELD);

    // 4) layer-1 self terms (lin_r + bias), fused across edge types per dst
    gemm_proj<<<(N_PAPER  + 63) / 64, TPB>>>(x_paper,  wsum1p, bsum1p, p1, N_PAPER);
    gemm_proj<<<(N_AUTHOR + 63) / 64, TPB>>>(x_author, wr1_rw, b1_rw,  a1, N_AUTHOR);
    gemm_proj<<<(N_FIELD  + 63) / 64, TPB>>>(x_field,  wr1_ht, b1_ht,  f1, N_FIELD);

    // 5) degree counts (wr/ci/rh reused by layer 2)
    count_kernel<<<(E_WR + TPB - 1) / TPB, TPB>>>(ei_wr + E_WR, cnt_wr, E_WR);
    count_kernel<<<(E_CI + TPB - 1) / TPB, TPB>>>(ei_ci + E_CI, cnt_ci, E_CI);
    count_kernel<<<(E_RH + TPB - 1) / TPB, TPB>>>(ei_rh + E_RH, cnt_rh, E_RH);
    count_kernel<<<(E_RW + TPB - 1) / TPB, TPB>>>(ei_rw + E_RW, cnt_rw, E_RW);
    count_kernel<<<(E_HT + TPB - 1) / TPB, TPB>>>(ei_ht + E_HT, cnt_ht, E_HT);

    // 6) layer-1 scatter (64-dim, float4 atomics)
    scatter64<<<(E_WR * 16 + TPB - 1) / TPB, TPB>>>((const float4*)h_wr, ei_wr, E_WR, (float4*)acc_p_wr);
    scatter64<<<(E_CI * 16 + TPB - 1) / TPB, TPB>>>((const float4*)h_ci, ei_ci, E_CI, (float4*)acc_p_ci);
    scatter64<<<(E_RH * 16 + TPB - 1) / TPB, TPB>>>((const float4*)h_rh, ei_rh, E_RH, (float4*)acc_p_rh);
    scatter64<<<(E_RW * 16 + TPB - 1) / TPB, TPB>>>((const float4*)h_rw, ei_rw, E_RW, (float4*)acc_a);
    scatter64<<<(E_HT * 16 + TPB - 1) / TPB, TPB>>>((const float4*)h_ht, ei_ht, E_HT, (float4*)acc_f);

    // 7) layer-1 finalize: mean + self + relu
    fin_paper<<<(N_PAPER * HID + TPB - 1) / TPB, TPB>>>(p1, acc_p_wr, acc_p_ci, acc_p_rh,
                                                        cnt_wr, cnt_ci, cnt_rh, N_PAPER);
    fin_one<<<(N_AUTHOR * HID + TPB - 1) / TPB, TPB>>>(a1, acc_a, cnt_rw, N_AUTHOR);
    fin_one<<<(N_FIELD  * HID + TPB - 1) / TPB, TPB>>>(f1, acc_f, cnt_ht, N_FIELD);

    // 8) layer-2 scatter (aggregate 64-dim hidden, then project)
    scatter64<<<(E_WR * 16 + TPB - 1) / TPB, TPB>>>((const float4*)a1, ei_wr, E_WR, (float4*)acc2_wr);
    scatter64<<<(E_CI * 16 + TPB - 1) / TPB, TPB>>>((const float4*)p1, ei_ci, E_CI, (float4*)acc2_ci);
    scatter64<<<(E_RH * 16 + TPB - 1) / TPB, TPB>>>((const float4*)f1, ei_rh, E_RH, (float4*)acc2_rh);

    // 9) fused output GEMM: [100k x 256] @ [256 x 349] + bias (mean folded into A-load)
    {
        dim3 grid((N_PAPER + 63) / 64, (OUTF + 63) / 64);
        gemm_out<<<grid, TPB>>>(acc2_wr, acc2_ci, acc2_rh, p1,
                                wl2_wr, wl2_ci, wl2_rh, wsum2,
                                cnt_wr, cnt_ci, cnt_rh,
                                bsum2, out, N_PAPER);
    }
}

// round 6
// speedup vs baseline: 1.5326x; 1.5326x over previous
#include <cuda_runtime.h>
#include <cstdint>

// ---------------- problem constants ----------------
#define N_PAPER  100000
#define N_AUTHOR 100000
#define N_FIELD  50000
#define F_IN 128
#define HID  64
#define OUTF 349
#define E_WR 1000000
#define E_RW 1000000
#define E_CI 2000000
#define E_HT 1000000
#define E_RH 1000000

// ---------------- scratch (static device memory; no allocs) ----------------
__device__ float g_h_wr[N_AUTHOR * HID];
__device__ float g_h_rw[N_PAPER  * HID];
__device__ float g_h_ci[N_PAPER  * HID];
__device__ float g_h_ht[N_PAPER  * HID];
__device__ float g_h_rh[N_FIELD  * HID];

__device__ float g_p1[N_PAPER  * HID];
__device__ float g_a1[N_AUTHOR * HID];
__device__ float g_f1[N_FIELD  * HID];

__device__ float g_wsum1p[F_IN * HID];
__device__ float g_bsum1p[HID];
__device__ float g_wsum2[HID * OUTF];
__device__ float g_bsum2[OUTF];

#define OFF_ACC_P_WR 0
#define OFF_ACC_P_CI (OFF_ACC_P_WR + N_PAPER * HID)
#define OFF_ACC_P_RH (OFF_ACC_P_CI + N_PAPER * HID)
#define OFF_ACC_A    (OFF_ACC_P_RH + N_PAPER * HID)
#define OFF_ACC_F    (OFF_ACC_A    + N_AUTHOR * HID)
#define OFF_CNT_WR   (OFF_ACC_F    + N_FIELD * HID)
#define OFF_CNT_CI   (OFF_CNT_WR   + N_PAPER)
#define OFF_CNT_RH   (OFF_CNT_CI   + N_PAPER)
#define OFF_CNT_RW   (OFF_CNT_RH   + N_PAPER)
#define OFF_CNT_HT   (OFF_CNT_RW   + N_AUTHOR)
#define OFF_ACC2_WR  (OFF_CNT_HT   + N_FIELD)
#define OFF_ACC2_CI  (OFF_ACC2_WR  + N_PAPER * HID)
#define OFF_ACC2_RH  (OFF_ACC2_CI  + N_PAPER * HID)
#define ACC_TOTAL    (OFF_ACC2_RH  + N_PAPER * HID)
__device__ float g_acc[ACC_TOTAL];

// ---------------- small helper kernels ----------------

__global__ void zero_kernel(float4* __restrict__ p, int n4) {
    int idx = blockIdx.x * blockDim.x + threadIdx.x;
    if (idx < n4) p[idx] = make_float4(0.f, 0.f, 0.f, 0.f);
}

__global__ void wsum3_kernel(const float* __restrict__ w0, const float* __restrict__ w1,
                             const float* __restrict__ w2, float* __restrict__ out, int n) {
    int idx = blockIdx.x * blockDim.x + threadIdx.x;
    if (idx < n) out[idx] = w0[idx] + w1[idx] + w2[idx];
}

// scatter-add 64-dim features + fused degree count (cnt may be null)
__global__ void scatter64(const float4* __restrict__ h, const int* __restrict__ ei, int E,
                          float4* __restrict__ acc, float* __restrict__ cnt) {
    const int* src = ei;
    const int* dst = ei + E;
    int n = E * 16;
    int idx = blockIdx.x * blockDim.x + threadIdx.x;
    if (idx < n) {
        int e = idx >> 4, c = idx & 15;
        int s = __ldg(&src[e]);
        int d = __ldg(&dst[e]);
        float4 v = h[s * 16 + c];
        atomicAdd(&acc[d * 16 + c], v);
        if (cnt && c == 0) atomicAdd(&cnt[d], 1.0f);
    }
}

__global__ void fin_paper(float* __restrict__ p,
                          const float* __restrict__ a0, const float* __restrict__ a1,
                          const float* __restrict__ a2,
                          const float* __restrict__ c0, const float* __restrict__ c1,
                          const float* __restrict__ c2, int N) {
    int idx = blockIdx.x * blockDim.x + threadIdx.x;
    if (idx < N * HID) {
        int row = idx >> 6;
        float r0 = 1.0f / fmaxf(c0[row], 1.0f);
        float r1 = 1.0f / fmaxf(c1[row], 1.0f);
        float r2 = 1.0f / fmaxf(c2[row], 1.0f);
        float v = p[idx] + a0[idx] * r0 + a1[idx] * r1 + a2[idx] * r2;
        p[idx] = fmaxf(v, 0.0f);
    }
}

__global__ void fin_one(float* __restrict__ y, const float* __restrict__ a,
                        const float* __restrict__ c, int N) {
    int idx = blockIdx.x * blockDim.x + threadIdx.x;
    if (idx < N * HID) {
        int row = idx >> 6;
        float r = 1.0f / fmaxf(c[row], 1.0f);
        y[idx] = fmaxf(y[idx] + a[idx] * r, 0.0f);
    }
}

// ---------------- tf32 tensor-core GEMMs ----------------

__device__ __forceinline__ unsigned f2tf(float f) {
    unsigned u;
    asm("cvt.rna.tf32.f32 %0, %1;" : "=r"(u) : "f"(f));
    return u;
}

__device__ __forceinline__ void mma8(float* c, const unsigned* a, const unsigned* b) {
    asm volatile("mma.sync.aligned.m16n8k8.row.col.f32.tf32.tf32.f32 "
        "{%0,%1,%2,%3}, {%4,%5,%6,%7}, {%8,%9}, {%0,%1,%2,%3};"
        : "+f"(c[0]), "+f"(c[1]), "+f"(c[2]), "+f"(c[3])
        : "r"(a[0]), "r"(a[1]), "r"(a[2]), "r"(a[3]), "r"(b[0]), "r"(b[1]));
}

#define ASTR 36   // 32 k-cols + pad; bank stride 4 -> frag reads conflict-free
#define BSTR 72   // 64 n-cols + pad; bank stride 8 -> frag reads conflict-free

// C[M x 64] = A[M x 128] @ W[128 x 64] (+ bias), tf32 tensor cores.
// block: 256 threads = 8 warps, tile 128x64, warp tile 32x32, K chunked at 32.
// Static smem: 128*36*4 + 32*72*4 = 27648 B.
__global__ __launch_bounds__(256) void gemm_proj_tc(
    const float* __restrict__ A, const float* __restrict__ W,
    const float* __restrict__ bias, float* __restrict__ C, int M)
{
    __shared__ unsigned As[128][ASTR];
    __shared__ unsigned Ws[32][BSTR];
    const int tid = threadIdx.x;
    const int warp = tid >> 5, lane = tid & 31;
    const int gid = lane >> 2, tig = lane & 3;
    const int wm = (warp & 3) * 32;
    const int wn = (warp >> 2) * 32;
    const int row0 = blockIdx.x * 128;

    float acc[2][4][4] = {};

    for (int kk = 0; kk < F_IN; kk += 32) {
        // A chunk: 128 rows x 32 k (8 float4 per row)
        for (int i = tid; i < 128 * 8; i += 256) {
            int r = i >> 3, q = i & 7;
            int rg = row0 + r;
            float4 v = make_float4(0.f, 0.f, 0.f, 0.f);
            if (rg < M) v = *(const float4*)&A[rg * F_IN + kk + q * 4];
            *(uint4*)&As[r][q * 4] = make_uint4(f2tf(v.x), f2tf(v.y), f2tf(v.z), f2tf(v.w));
        }
        // W chunk: 32 k x 64 n (16 float4 per k-row)
        for (int i = tid; i < 32 * 16; i += 256) {
            int k = i >> 4, q = i & 15;
            float4 v = *(const float4*)&W[(kk + k) * HID + q * 4];
            *(uint4*)&Ws[k][q * 4] = make_uint4(f2tf(v.x), f2tf(v.y), f2tf(v.z), f2tf(v.w));
        }
        __syncthreads();
        #pragma unroll
        for (int kt = 0; kt < 4; kt++) {
            int k0 = kt * 8;
            unsigned a[2][4], b[4][2];
            #pragma unroll
            for (int mi = 0; mi < 2; mi++) {
                int r = wm + mi * 16 + gid;
                a[mi][0] = As[r][k0 + tig];
                a[mi][1] = As[r + 8][k0 + tig];
                a[mi][2] = As[r][k0 + tig + 4];
                a[mi][3] = As[r + 8][k0 + tig + 4];
            }
            #pragma unroll
            for (int ni = 0; ni < 4; ni++) {
                int n = wn + ni * 8 + gid;
                b[ni][0] = Ws[k0 + tig][n];
                b[ni][1] = Ws[k0 + tig + 4][n];
            }
            #pragma unroll
            for (int mi = 0; mi < 2; mi++)
                #pragma unroll
                for (int ni = 0; ni < 4; ni++)
                    mma8(acc[mi][ni], a[mi], b[ni]);
        }
        __syncthreads();
    }

    #pragma unroll
    for (int ni = 0; ni < 4; ni++) {
        int col = wn + ni * 8 + tig * 2;
        float2 bv = make_float2(0.f, 0.f);
        if (bias) bv = *(const float2*)&bias[col];
        #pragma unroll
        for (int mi = 0; mi < 2; mi++) {
            int r = row0 + wm + mi * 16 + gid;
            if (r < M)
                *(float2*)&C[r * HID + col] =
                    make_float2(acc[mi][ni][0] + bv.x, acc[mi][ni][1] + bv.y);
            if (r + 8 < M)
                *(float2*)&C[(r + 8) * HID + col] =
                    make_float2(acc[mi][ni][2] + bv.x, acc[mi][ni][3] + bv.y);
        }
    }
}

// C[M x 349] = sum_t Ahat_t[M x 64] @ W_t[64 x 349] + bias  (tf32 TC)
//   t<3: Ahat_t = A_t / max(cnt_t,1);  t=3: Ahat = A_3 (self)
// Same tile scheme; K per t chunked at 32 (2 chunks), 4 t's = 8 smem sweeps.
__global__ __launch_bounds__(256) void gemm_out_tc(
    const float* __restrict__ A0, const float* __restrict__ A1,
    const float* __restrict__ A2, const float* __restrict__ A3,
    const float* __restrict__ W0, const float* __restrict__ W1,
    const float* __restrict__ W2, const float* __restrict__ W3,
    const float* __restrict__ c0, const float* __restrict__ c1,
    const float* __restrict__ c2,
    const float* __restrict__ bias, float* __restrict__ C, int M)
{
    __shared__ unsigned As[128][ASTR];
    __shared__ unsigned Ws[32][BSTR];
    const int tid = threadIdx.x;
    const int warp = tid >> 5, lane = tid & 31;
    const int gid = lane >> 2, tig = lane & 3;
    const int wm = (warp & 3) * 32;
    const int wn = (warp >> 2) * 32;
    const int row0 = blockIdx.x * 128;
    const int col0 = blockIdx.y * 64;

    const float* Aps[4] = {A0, A1, A2, A3};
    const float* Wps[4] = {W0, W1, W2, W3};
    const float* cps[4] = {c0, c1, c2, nullptr};

    float acc[2][4][4] = {};

    #pragma unroll 1
    for (int t = 0; t < 4; t++) {
        const float* A = Aps[t];
        const float* W = Wps[t];
        const float* cp = cps[t];
        #pragma unroll 1
        for (int kc = 0; kc < HID; kc += 32) {
            for (int i = tid; i < 128 * 8; i += 256) {
                int r = i >> 3, q = i & 7;
                int rg = row0 + r;
                float4 v = make_float4(0.f, 0.f, 0.f, 0.f);
                if (rg < M) {
                    v = *(const float4*)&A[rg * HID + kc + q * 4];
                    if (cp) {
                        float s = 1.0f / fmaxf(cp[rg], 1.0f);
                        v.x *= s; v.y *= s; v.z *= s; v.w *= s;
                    }
                }
                *(uint4*)&As[r][q * 4] = make_uint4(f2tf(v.x), f2tf(v.y), f2tf(v.z), f2tf(v.w));
            }
            for (int i = tid; i < 32 * 64; i += 256) {
                int k = i >> 6, n = i & 63;
                int cg = col0 + n;
                float v = (cg < OUTF) ? W[(kc + k) * OUTF + cg] : 0.f;
                Ws[k][n] = f2tf(v);
            }
            __syncthreads();
            #pragma unroll
            for (int kt = 0; kt < 4; kt++) {
                int k0 = kt * 8;
                unsigned a[2][4], b[4][2];
                #pragma unroll
                for (int mi = 0; mi < 2; mi++) {
                    int r = wm + mi * 16 + gid;
                    a[mi][0] = As[r][k0 + tig];
                    a[mi][1] = As[r + 8][k0 + tig];
                    a[mi][2] = As[r][k0 + tig + 4];
                    a[mi][3] = As[r + 8][k0 + tig + 4];
                }
                #pragma unroll
                for (int ni = 0; ni < 4; ni++) {
                    int n = wn + ni * 8 + gid;
                    b[ni][0] = Ws[k0 + tig][n];
                    b[ni][1] = Ws[k0 + tig + 4][n];
                }
                #pragma unroll
                for (int mi = 0; mi < 2; mi++)
                    #pragma unroll
                    for (int ni = 0; ni < 4; ni++)
                        mma8(acc[mi][ni], a[mi], b[ni]);
            }
            __syncthreads();
        }
    }

    #pragma unroll
    for (int ni = 0; ni < 4; ni++) {
        int col = col0 + wn + ni * 8 + tig * 2;
        float b0v = (col < OUTF) ? bias[col] : 0.f;
        float b1v = (col + 1 < OUTF) ? bias[col + 1] : 0.f;
        #pragma unroll
        for (int mi = 0; mi < 2; mi++) {
            int r = row0 + wm + mi * 16 + gid;
            if (r < M) {
                if (col < OUTF)     C[r * OUTF + col]     = acc[mi][ni][0] + b0v;
                if (col + 1 < OUTF) C[r * OUTF + col + 1] = acc[mi][ni][1] + b1v;
            }
            int r2 = r + 8;
            if (r2 < M) {
                if (col < OUTF)     C[r2 * OUTF + col]     = acc[mi][ni][2] + b0v;
                if (col + 1 < OUTF) C[r2 * OUTF + col + 1] = acc[mi][ni][3] + b1v;
            }
        }
    }
}

// ---------------- host launcher ----------------
extern "C" void kernel_launch(void* const* d_in, const int* in_sizes, int n_in,
                              void* d_out, int out_size) {
    (void)in_sizes; (void)n_in; (void)out_size;
    const float* x_paper  = (const float*)d_in[0];
    const float* x_author = (const float*)d_in[1];
    const float* x_field  = (const float*)d_in[2];
    const int* ei_wr = (const int*)d_in[3];
    const int* ei_rw = (const int*)d_in[4];
    const int* ei_ci = (const int*)d_in[5];
    const int* ei_ht = (const int*)d_in[6];
    const int* ei_rh = (const int*)d_in[7];
    const float* wl1_wr = (const float*)d_in[8];
    const float* wr1_wr = (const float*)d_in[9];
    const float* b1_wr  = (const float*)d_in[10];
    const float* wl1_rw = (const float*)d_in[11];
    const float* wr1_rw = (const float*)d_in[12];
    const float* b1_rw  = (const float*)d_in[13];
    const float* wl1_ci = (const float*)d_in[14];
    const float* wr1_ci = (const float*)d_in[15];
    const float* b1_ci  = (const float*)d_in[16];
    const float* wl1_ht = (const float*)d_in[17];
    const float* wr1_ht = (const float*)d_in[18];
    const float* b1_ht  = (const float*)d_in[19];
    const float* wl1_rh = (const float*)d_in[20];
    const float* wr1_rh = (const float*)d_in[21];
    const float* b1_rh  = (const float*)d_in[22];
    const float* wl2_wr = (const float*)d_in[23];
    const float* wr2_wr = (const float*)d_in[24];
    const float* b2_wr  = (const float*)d_in[25];
    const float* wl2_ci = (const float*)d_in[26];
    const float* wr2_ci = (const float*)d_in[27];
    const float* b2_ci  = (const float*)d_in[28];
    const float* wl2_rh = (const float*)d_in[29];
    const float* wr2_rh = (const float*)d_in[30];
    const float* b2_rh  = (const float*)d_in[31];
    float* out = (float*)d_out;

    float *h_wr, *h_rw, *h_ci, *h_ht, *h_rh, *p1, *a1, *f1;
    float *wsum1p, *bsum1p, *wsum2, *bsum2, *accb;
    cudaGetSymbolAddress((void**)&h_wr, g_h_wr);
    cudaGetSymbolAddress((void**)&h_rw, g_h_rw);
    cudaGetSymbolAddress((void**)&h_ci, g_h_ci);
    cudaGetSymbolAddress((void**)&h_ht, g_h_ht);
    cudaGetSymbolAddress((void**)&h_rh, g_h_rh);
    cudaGetSymbolAddress((void**)&p1, g_p1);
    cudaGetSymbolAddress((void**)&a1, g_a1);
    cudaGetSymbolAddress((void**)&f1, g_f1);
    cudaGetSymbolAddress((void**)&wsum1p, g_wsum1p);
    cudaGetSymbolAddress((void**)&bsum1p, g_bsum1p);
    cudaGetSymbolAddress((void**)&wsum2, g_wsum2);
    cudaGetSymbolAddress((void**)&bsum2, g_bsum2);
    cudaGetSymbolAddress((void**)&accb, g_acc);

    float* acc_p_wr = accb + OFF_ACC_P_WR;
    float* acc_p_ci = accb + OFF_ACC_P_CI;
    float* acc_p_rh = accb + OFF_ACC_P_RH;
    float* acc_a    = accb + OFF_ACC_A;
    float* acc_f    = accb + OFF_ACC_F;
    float* cnt_wr   = accb + OFF_CNT_WR;
    float* cnt_ci   = accb + OFF_CNT_CI;
    float* cnt_rh   = accb + OFF_CNT_RH;
    float* cnt_rw   = accb + OFF_CNT_RW;
    float* cnt_ht   = accb + OFF_CNT_HT;
    float* acc2_wr  = accb + OFF_ACC2_WR;
    float* acc2_ci  = accb + OFF_ACC2_CI;
    float* acc2_rh  = accb + OFF_ACC2_RH;

    const int TPB = 256;

    // 1) zero accumulators + counts
    {
        int n4 = ACC_TOTAL / 4;
        zero_kernel<<<(n4 + TPB - 1) / TPB, TPB>>>((float4*)accb, n4);
    }

    // 2) summed self-weights/biases
    wsum3_kernel<<<(F_IN * HID + TPB - 1) / TPB, TPB>>>(wr1_wr, wr1_ci, wr1_rh, wsum1p, F_IN * HID);
    wsum3_kernel<<<1, TPB>>>(b1_wr, b1_ci, b1_rh, bsum1p, HID);
    wsum3_kernel<<<(HID * OUTF + TPB - 1) / TPB, TPB>>>(wr2_wr, wr2_ci, wr2_rh, wsum2, HID * OUTF);
    wsum3_kernel<<<(OUTF + TPB - 1) / TPB, TPB>>>(b2_wr, b2_ci, b2_rh, bsum2, OUTF);

    // 3) layer-1 source projections (lin_l), tf32 TC
    gemm_proj_tc<<<(N_AUTHOR + 127) / 128, TPB>>>(x_author, wl1_wr, nullptr, h_wr, N_AUTHOR);
    gemm_proj_tc<<<(N_PAPER  + 127) / 128, TPB>>>(x_paper,  wl1_rw, nullptr, h_rw, N_PAPER);
    gemm_proj_tc<<<(N_PAPER  + 127) / 128, TPB>>>(x_paper,  wl1_ci, nullptr, h_ci, N_PAPER);
    gemm_proj_tc<<<(N_PAPER  + 127) / 128, TPB>>>(x_paper,  wl1_ht, nullptr, h_ht, N_PAPER);
    gemm_proj_tc<<<(N_FIELD  + 127) / 128, TPB>>>(x_field,  wl1_rh, nullptr, h_rh, N_FIELD);

    // 4) layer-1 self terms (lin_r + bias), fused across edge types per dst
    gemm_proj_tc<<<(N_PAPER  + 127) / 128, TPB>>>(x_paper,  wsum1p, bsum1p, p1, N_PAPER);
    gemm_proj_tc<<<(N_AUTHOR + 127) / 128, TPB>>>(x_author, wr1_rw, b1_rw,  a1, N_AUTHOR);
    gemm_proj_tc<<<(N_FIELD  + 127) / 128, TPB>>>(x_field,  wr1_ht, b1_ht,  f1, N_FIELD);

    // 5) layer-1 scatter (64-dim float4 atomics) with fused degree counts
    scatter64<<<(E_WR * 16 + TPB - 1) / TPB, TPB>>>((const float4*)h_wr, ei_wr, E_WR, (float4*)acc_p_wr, cnt_wr);
    scatter64<<<(E_CI * 16 + TPB - 1) / TPB, TPB>>>((const float4*)h_ci, ei_ci, E_CI, (float4*)acc_p_ci, cnt_ci);
    scatter64<<<(E_RH * 16 + TPB - 1) / TPB, TPB>>>((const float4*)h_rh, ei_rh, E_RH, (float4*)acc_p_rh, cnt_rh);
    scatter64<<<(E_RW * 16 + TPB - 1) / TPB, TPB>>>((const float4*)h_rw, ei_rw, E_RW, (float4*)acc_a, cnt_rw);
    scatter64<<<(E_HT * 16 + TPB - 1) / TPB, TPB>>>((const float4*)h_ht, ei_ht, E_HT, (float4*)acc_f, cnt_ht);

    // 6) layer-1 finalize: mean + self + relu
    fin_paper<<<(N_PAPER * HID + TPB - 1) / TPB, TPB>>>(p1, acc_p_wr, acc_p_ci, acc_p_rh,
                                                        cnt_wr, cnt_ci, cnt_rh, N_PAPER);
    fin_one<<<(N_AUTHOR * HID + TPB - 1) / TPB, TPB>>>(a1, acc_a, cnt_rw, N_AUTHOR);
    fin_one<<<(N_FIELD  * HID + TPB - 1) / TPB, TPB>>>(f1, acc_f, cnt_ht, N_FIELD);

    // 7) layer-2 scatter (aggregate 64-dim hidden, then project)
    scatter64<<<(E_WR * 16 + TPB - 1) / TPB, TPB>>>((const float4*)a1, ei_wr, E_WR, (float4*)acc2_wr, nullptr);
    scatter64<<<(E_CI * 16 + TPB - 1) / TPB, TPB>>>((const float4*)p1, ei_ci, E_CI, (float4*)acc2_ci, nullptr);
    scatter64<<<(E_RH * 16 + TPB - 1) / TPB, TPB>>>((const float4*)f1, ei_rh, E_RH, (float4*)acc2_rh, nullptr);

    // 8) fused output GEMM: [100k x 4x64] @ [4x64 x 349] + bias, tf32 TC
    {
        dim3 grid((N_PAPER + 127) / 128, (OUTF + 63) / 64);
        gemm_out_tc<<<grid, TPB>>>(acc2_wr, acc2_ci, acc2_rh, p1,
                                   wl2_wr, wl2_ci, wl2_rh, wsum2,
                                   cnt_wr, cnt_ci, cnt_rh,
                                   bsum2, out, N_PAPER);
    }
}

// round 11
// speedup vs baseline: 2.1223x; 1.3848x over previous
#include <cuda_runtime.h>
#include <cstdint>

// ---------------- problem constants ----------------
#define N_PAPER  100000
#define N_AUTHOR 100000
#define N_FIELD  50000
#define F_IN 128
#define HID  64
#define OUTF 349
#define E_WR 1000000
#define E_RW 1000000
#define E_CI 2000000
#define E_HT 1000000
#define E_RH 1000000
#define E_TOT 6000000

// global (node,type) slot bases for the concatenated CSR
#define B_WR 0          // dst = paper
#define B_CI 100000     // dst = paper
#define B_RH 200000     // dst = paper
#define B_RW 300000     // dst = author
#define B_HT 400000     // dst = field
#define NTOT 450000

// ---------------- scratch (static device memory; no allocs) ----------------
__device__ float g_h_wr[N_AUTHOR * HID];
__device__ float g_h_rw[N_PAPER  * HID];
__device__ float g_h_ci[N_PAPER  * HID];
__device__ float g_h_ht[N_PAPER  * HID];
__device__ float g_h_rh[N_FIELD  * HID];

__device__ float g_p1[N_PAPER  * HID];
__device__ float g_a1[N_AUTHOR * HID];
__device__ float g_f1[N_FIELD  * HID];

__device__ float g_acc2_wr[N_PAPER * HID];
__device__ float g_acc2_ci[N_PAPER * HID];
__device__ float g_acc2_rh[N_PAPER * HID];

__device__ float g_wsum1p[F_IN * HID];
__device__ float g_bsum1p[HID];
__device__ float g_wsum2[HID * OUTF];
__device__ float g_bsum2[OUTF];

__device__ int g_cnt[NTOT];
__device__ int g_rowptr[NTOT + 1];
__device__ int g_cursor[NTOT];
__device__ int g_partials[512];
__device__ int g_csr[E_TOT];

// ---------------- small helper kernels ----------------

__global__ void zero_cnt_kernel(int4* __restrict__ p, int n4) {
    int idx = blockIdx.x * blockDim.x + threadIdx.x;
    if (idx < n4) p[idx] = make_int4(0, 0, 0, 0);
}

__global__ void wsum3_kernel(const float* __restrict__ w0, const float* __restrict__ w1,
                             const float* __restrict__ w2, float* __restrict__ out, int n) {
    int idx = blockIdx.x * blockDim.x + threadIdx.x;
    if (idx < n) out[idx] = w0[idx] + w1[idx] + w2[idx];
}

__global__ void count_kernel(const int* __restrict__ dst, int* __restrict__ cnt, int E) {
    int idx = blockIdx.x * blockDim.x + threadIdx.x;
    if (idx < E) atomicAdd(&cnt[__ldg(&dst[idx])], 1);
}

// ---- fused exclusive scan over 450k counts (3 kernels) ----
// scan1: per-block (1024 elems, 256 thr x 4) exclusive scan + block totals
__global__ void scan1_kernel(const int* __restrict__ cnt, int* __restrict__ rp,
                             int* __restrict__ partials) {
    __shared__ int s[256];
    int t = threadIdx.x, b = blockIdx.x;
    int i0 = b * 1024 + t * 4;
    int c0 = (i0     < NTOT) ? cnt[i0]     : 0;
    int c1 = (i0 + 1 < NTOT) ? cnt[i0 + 1] : 0;
    int c2 = (i0 + 2 < NTOT) ? cnt[i0 + 2] : 0;
    int c3 = (i0 + 3 < NTOT) ? cnt[i0 + 3] : 0;
    int ts = c0 + c1 + c2 + c3;
    s[t] = ts;
    __syncthreads();
    for (int off = 1; off < 256; off <<= 1) {
        int v = (t >= off) ? s[t - off] : 0;
        __syncthreads();
        s[t] += v;
        __syncthreads();
    }
    int p = s[t] - ts;                 // exclusive prefix of this thread's quad
    if (t == 255) partials[b] = s[255];
    if (i0     < NTOT) rp[i0]     = p; p += c0;
    if (i0 + 1 < NTOT) rp[i0 + 1] = p; p += c1;
    if (i0 + 2 < NTOT) rp[i0 + 2] = p; p += c2;
    if (i0 + 3 < NTOT) rp[i0 + 3] = p;
}

// scan2: single-block exclusive scan of block partials
__global__ void scan2_kernel(int* __restrict__ partials, int nblk) {
    __shared__ int s[512];
    int t = threadIdx.x;
    int v0 = (t < nblk) ? partials[t] : 0;
    s[t] = v0;
    __syncthreads();
    for (int off = 1; off < 512; off <<= 1) {
        int v = (t >= off) ? s[t - off] : 0;
        __syncthreads();
        s[t] += v;
        __syncthreads();
    }
    if (t < nblk) partials[t] = s[t] - v0;   // exclusive
}

// scan3: add block offsets; init cursor; set sentinel
__global__ void scan3_kernel(int* __restrict__ rp, const int* __restrict__ partials,
                             int* __restrict__ cursor) {
    int i = blockIdx.x * blockDim.x + threadIdx.x;
    if (i < NTOT) {
        int v = rp[i] + partials[i >> 10];
        rp[i] = v;
        cursor[i] = v;
    }
    if (i == 0) rp[NTOT] = E_TOT;
}

// reorder: csr[pos] = src, pos allocated via cursor
__global__ void reorder_kernel(const int* __restrict__ ei, int E, int gbase,
                               int* __restrict__ cursor, int* __restrict__ csr) {
    int e = blockIdx.x * blockDim.x + threadIdx.x;
    if (e < E) {
        int s = __ldg(&ei[e]);
        int d = __ldg(&ei[E + e]);
        int pos = atomicAdd(&cursor[gbase + d], 1);
        csr[pos] = s;
    }
}

// ---- CSR-based aggregation: warp per destination, float2 per lane ----

// paper layer-1, fully fused: p = relu(p_self + mean_wr + mean_ci + mean_rh)
__global__ void agg_paper_fin(const float2* __restrict__ hwr, const float2* __restrict__ hci,
                              const float2* __restrict__ hrh,
                              const int* __restrict__ csr, const int* __restrict__ rp,
                              float2* __restrict__ p) {
    int gw = (blockIdx.x * blockDim.x + threadIdx.x) >> 5;
    int lane = threadIdx.x & 31;
    if (gw >= N_PAPER) return;
    float2 tot = p[gw * 32 + lane];
    const float2* feats[3] = {hwr, hci, hrh};
    #pragma unroll
    for (int t = 0; t < 3; t++) {
        int s = __ldg(&rp[t * 100000 + gw]);
        int e = __ldg(&rp[t * 100000 + gw + 1]);
        float2 acc = make_float2(0.f, 0.f);
        const float2* f = feats[t];
        #pragma unroll 4
        for (int i = s; i < e; i++) {
            int sv = __ldg(&csr[i]);
            float2 v = __ldg(&f[sv * 32 + lane]);
            acc.x += v.x; acc.y += v.y;
        }
        float r = (e > s) ? 1.0f / (float)(e - s) : 0.f;
        tot.x += acc.x * r; tot.y += acc.y * r;
    }
    p[gw * 32 + lane] = make_float2(fmaxf(tot.x, 0.f), fmaxf(tot.y, 0.f));
}

// y = relu(y + mean over one segment)
__global__ void agg_fin_one(const float2* __restrict__ feat, const int* __restrict__ csr,
                            const int* __restrict__ rp, int base, int n,
                            float2* __restrict__ y) {
    int gw = (blockIdx.x * blockDim.x + threadIdx.x) >> 5;
    int lane = threadIdx.x & 31;
    if (gw >= n) return;
    int s = __ldg(&rp[base + gw]);
    int e = __ldg(&rp[base + gw + 1]);
    float2 acc = make_float2(0.f, 0.f);
    #pragma unroll 4
    for (int i = s; i < e; i++) {
        int sv = __ldg(&csr[i]);
        float2 v = __ldg(&feat[sv * 32 + lane]);
        acc.x += v.x; acc.y += v.y;
    }
    float r = (e > s) ? 1.0f / (float)(e - s) : 0.f;
    float2 t = y[gw * 32 + lane];
    y[gw * 32 + lane] = make_float2(fmaxf(t.x + acc.x * r, 0.f),
                                    fmaxf(t.y + acc.y * r, 0.f));
}

// out = mean over one segment (plain write; deg-0 -> 0)
__global__ void agg_mean(const float2* __restrict__ feat, const int* __restrict__ csr,
                         const int* __restrict__ rp, int base, int n,
                         float2* __restrict__ out) {
    int gw = (blockIdx.x * blockDim.x + threadIdx.x) >> 5;
    int lane = threadIdx.x & 31;
    if (gw >= n) return;
    int s = __ldg(&rp[base + gw]);
    int e = __ldg(&rp[base + gw + 1]);
    float2 acc = make_float2(0.f, 0.f);
    #pragma unroll 4
    for (int i = s; i < e; i++) {
        int sv = __ldg(&csr[i]);
        float2 v = __ldg(&feat[sv * 32 + lane]);
        acc.x += v.x; acc.y += v.y;
    }
    float r = (e > s) ? 1.0f / (float)(e - s) : 0.f;
    out[gw * 32 + lane] = make_float2(acc.x * r, acc.y * r);
}

// ---------------- tf32 tensor-core GEMMs ----------------

__device__ __forceinline__ unsigned f2tf(float f) {
    unsigned u;
    asm("cvt.rna.tf32.f32 %0, %1;" : "=r"(u) : "f"(f));
    return u;
}

__device__ __forceinline__ void mma8(float* c, const unsigned* a, const unsigned* b) {
    asm volatile("mma.sync.aligned.m16n8k8.row.col.f32.tf32.tf32.f32 "
        "{%0,%1,%2,%3}, {%4,%5,%6,%7}, {%8,%9}, {%0,%1,%2,%3};"
        : "+f"(c[0]), "+f"(c[1]), "+f"(c[2]), "+f"(c[3])
        : "r"(a[0]), "r"(a[1]), "r"(a[2]), "r"(a[3]), "r"(b[0]), "r"(b[1]));
}

#define ASTR 36
#define BSTR 72

// C[M x 64] = A[M x 128] @ W[128 x 64] (+ bias), tf32 TC
__global__ __launch_bounds__(256) void gemm_proj_tc(
    const float* __restrict__ A, const float* __restrict__ W,
    const float* __restrict__ bias, float* __restrict__ C, int M)
{
    __shared__ unsigned As[128][ASTR];
    __shared__ unsigned Ws[32][BSTR];
    const int tid = threadIdx.x;
    const int warp = tid >> 5, lane = tid & 31;
    const int gid = lane >> 2, tig = lane & 3;
    const int wm = (warp & 3) * 32;
    const int wn = (warp >> 2) * 32;
    const int row0 = blockIdx.x * 128;

    float acc[2][4][4] = {};

    for (int kk = 0; kk < F_IN; kk += 32) {
        for (int i = tid; i < 128 * 8; i += 256) {
            int r = i >> 3, q = i & 7;
            int rg = row0 + r;
            float4 v = make_float4(0.f, 0.f, 0.f, 0.f);
            if (rg < M) v = *(const float4*)&A[rg * F_IN + kk + q * 4];
            *(uint4*)&As[r][q * 4] = make_uint4(f2tf(v.x), f2tf(v.y), f2tf(v.z), f2tf(v.w));
        }
        for (int i = tid; i < 32 * 16; i += 256) {
            int k = i >> 4, q = i & 15;
            float4 v = *(const float4*)&W[(kk + k) * HID + q * 4];
            *(uint4*)&Ws[k][q * 4] = make_uint4(f2tf(v.x), f2tf(v.y), f2tf(v.z), f2tf(v.w));
        }
        __syncthreads();
        #pragma unroll
        for (int kt = 0; kt < 4; kt++) {
            int k0 = kt * 8;
            unsigned a[2][4], b[4][2];
            #pragma unroll
            for (int mi = 0; mi < 2; mi++) {
                int r = wm + mi * 16 + gid;
                a[mi][0] = As[r][k0 + tig];
                a[mi][1] = As[r + 8][k0 + tig];
                a[mi][2] = As[r][k0 + tig + 4];
                a[mi][3] = As[r + 8][k0 + tig + 4];
            }
            #pragma unroll
            for (int ni = 0; ni < 4; ni++) {
                int n = wn + ni * 8 + gid;
                b[ni][0] = Ws[k0 + tig][n];
                b[ni][1] = Ws[k0 + tig + 4][n];
            }
            #pragma unroll
            for (int mi = 0; mi < 2; mi++)
                #pragma unroll
                for (int ni = 0; ni < 4; ni++)
                    mma8(acc[mi][ni], a[mi], b[ni]);
        }
        __syncthreads();
    }

    #pragma unroll
    for (int ni = 0; ni < 4; ni++) {
        int col = wn + ni * 8 + tig * 2;
        float2 bv = make_float2(0.f, 0.f);
        if (bias) bv = *(const float2*)&bias[col];
        #pragma unroll
        for (int mi = 0; mi < 2; mi++) {
            int r = row0 + wm + mi * 16 + gid;
            if (r < M)
                *(float2*)&C[r * HID + col] =
                    make_float2(acc[mi][ni][0] + bv.x, acc[mi][ni][1] + bv.y);
            if (r + 8 < M)
                *(float2*)&C[(r + 8) * HID + col] =
                    make_float2(acc[mi][ni][2] + bv.x, acc[mi][ni][3] + bv.y);
        }
    }
}

// C[M x 349] = sum_t A_t[M x 64] @ W_t[64 x 349] + bias  (A_t already mean-scaled)
__global__ __launch_bounds__(256) void gemm_out_tc(
    const float* __restrict__ A0, const float* __restrict__ A1,
    const float* __restrict__ A2, const float* __restrict__ A3,
    const float* __restrict__ W0, const float* __restrict__ W1,
    const float* __restrict__ W2, const float* __restrict__ W3,
    const float* __restrict__ bias, float* __restrict__ C, int M)
{
    __shared__ unsigned As[128][ASTR];
    __shared__ unsigned Ws[32][BSTR];
    const int tid = threadIdx.x;
    const int warp = tid >> 5, lane = tid & 31;
    const int gid = lane >> 2, tig = lane & 3;
    const int wm = (warp & 3) * 32;
    const int wn = (warp >> 2) * 32;
    const int row0 = blockIdx.x * 128;
    const int col0 = blockIdx.y * 64;

    const float* Aps[4] = {A0, A1, A2, A3};
    const float* Wps[4] = {W0, W1, W2, W3};

    float acc[2][4][4] = {};

    #pragma unroll 1
    for (int t = 0; t < 4; t++) {
        const float* A = Aps[t];
        const float* W = Wps[t];
        #pragma unroll 1
        for (int kc = 0; kc < HID; kc += 32) {
            for (int i = tid; i < 128 * 8; i += 256) {
                int r = i >> 3, q = i & 7;
                int rg = row0 + r;
                float4 v = make_float4(0.f, 0.f, 0.f, 0.f);
                if (rg < M) v = *(const float4*)&A[rg * HID + kc + q * 4];
                *(uint4*)&As[r][q * 4] = make_uint4(f2tf(v.x), f2tf(v.y), f2tf(v.z), f2tf(v.w));
            }
            for (int i = tid; i < 32 * 64; i += 256) {
                int k = i >> 6, n = i & 63;
                int cg = col0 + n;
                float v = (cg < OUTF) ? W[(kc + k) * OUTF + cg] : 0.f;
                Ws[k][n] = f2tf(v);
            }
            __syncthreads();
            #pragma unroll
            for (int kt = 0; kt < 4; kt++) {
                int k0 = kt * 8;
                unsigned a[2][4], b[4][2];
                #pragma unroll
                for (int mi = 0; mi < 2; mi++) {
                    int r = wm + mi * 16 + gid;
                    a[mi][0] = As[r][k0 + tig];
                    a[mi][1] = As[r + 8][k0 + tig];
                    a[mi][2] = As[r][k0 + tig + 4];
                    a[mi][3] = As[r + 8][k0 + tig + 4];
                }
                #pragma unroll
                for (int ni = 0; ni < 4; ni++) {
                    int n = wn + ni * 8 + gid;
                    b[ni][0] = Ws[k0 + tig][n];
                    b[ni][1] = Ws[k0 + tig + 4][n];
                }
                #pragma unroll
                for (int mi = 0; mi < 2; mi++)
                    #pragma unroll
                    for (int ni = 0; ni < 4; ni++)
                        mma8(acc[mi][ni], a[mi], b[ni]);
            }
            __syncthreads();
        }
    }

    #pragma unroll
    for (int ni = 0; ni < 4; ni++) {
        int col = col0 + wn + ni * 8 + tig * 2;
        float b0v = (col < OUTF) ? bias[col] : 0.f;
        float b1v = (col + 1 < OUTF) ? bias[col + 1] : 0.f;
        #pragma unroll
        for (int mi = 0; mi < 2; mi++) {
            int r = row0 + wm + mi * 16 + gid;
            if (r < M) {
                if (col < OUTF)     C[r * OUTF + col]     = acc[mi][ni][0] + b0v;
                if (col + 1 < OUTF) C[r * OUTF + col + 1] = acc[mi][ni][1] + b1v;
            }
            int r2 = r + 8;
            if (r2 < M) {
                if (col < OUTF)     C[r2 * OUTF + col]     = acc[mi][ni][2] + b0v;
                if (col + 1 < OUTF) C[r2 * OUTF + col + 1] = acc[mi][ni][3] + b1v;
            }
        }
    }
}

// ---------------- host launcher ----------------
extern "C" void kernel_launch(void* const* d_in, const int* in_sizes, int n_in,
                              void* d_out, int out_size) {
    (void)in_sizes; (void)n_in; (void)out_size;
    const float* x_paper  = (const float*)d_in[0];
    const float* x_author = (const float*)d_in[1];
    const float* x_field  = (const float*)d_in[2];
    const int* ei_wr = (const int*)d_in[3];
    const int* ei_rw = (const int*)d_in[4];
    const int* ei_ci = (const int*)d_in[5];
    const int* ei_ht = (const int*)d_in[6];
    const int* ei_rh = (const int*)d_in[7];
    const float* wl1_wr = (const float*)d_in[8];
    const float* wr1_wr = (const float*)d_in[9];
    const float* b1_wr  = (const float*)d_in[10];
    const float* wl1_rw = (const float*)d_in[11];
    const float* wr1_rw = (const float*)d_in[12];
    const float* b1_rw  = (const float*)d_in[13];
    const float* wl1_ci = (const float*)d_in[14];
    const float* wr1_ci = (const float*)d_in[15];
    const float* b1_ci  = (const float*)d_in[16];
    const float* wl1_ht = (const float*)d_in[17];
    const float* wr1_ht = (const float*)d_in[18];
    const float* b1_ht  = (const float*)d_in[19];
    const float* wl1_rh = (const float*)d_in[20];
    const float* wr1_rh = (const float*)d_in[21];
    const float* b1_rh  = (const float*)d_in[22];
    const float* wl2_wr = (const float*)d_in[23];
    const float* wr2_wr = (const float*)d_in[24];
    const float* b2_wr  = (const float*)d_in[25];
    const float* wl2_ci = (const float*)d_in[26];
    const float* wr2_ci = (const float*)d_in[27];
    const float* b2_ci  = (const float*)d_in[28];
    const float* wl2_rh = (const float*)d_in[29];
    const float* wr2_rh = (const float*)d_in[30];
    const float* b2_rh  = (const float*)d_in[31];
    float* out = (float*)d_out;

    float *h_wr, *h_rw, *h_ci, *h_ht, *h_rh, *p1, *a1, *f1;
    float *acc2_wr, *acc2_ci, *acc2_rh;
    float *wsum1p, *bsum1p, *wsum2, *bsum2;
    int *cnt, *rowptr, *cursor, *partials, *csr;
    cudaGetSymbolAddress((void**)&h_wr, g_h_wr);
    cudaGetSymbolAddress((void**)&h_rw, g_h_rw);
    cudaGetSymbolAddress((void**)&h_ci, g_h_ci);
    cudaGetSymbolAddress((void**)&h_ht, g_h_ht);
    cudaGetSymbolAddress((void**)&h_rh, g_h_rh);
    cudaGetSymbolAddress((void**)&p1, g_p1);
    cudaGetSymbolAddress((void**)&a1, g_a1);
    cudaGetSymbolAddress((void**)&f1, g_f1);
    cudaGetSymbolAddress((void**)&acc2_wr, g_acc2_wr);
    cudaGetSymbolAddress((void**)&acc2_ci, g_acc2_ci);
    cudaGetSymbolAddress((void**)&acc2_rh, g_acc2_rh);
    cudaGetSymbolAddress((void**)&wsum1p, g_wsum1p);
    cudaGetSymbolAddress((void**)&bsum1p, g_bsum1p);
    cudaGetSymbolAddress((void**)&wsum2, g_wsum2);
    cudaGetSymbolAddress((void**)&bsum2, g_bsum2);
    cudaGetSymbolAddress((void**)&cnt, g_cnt);
    cudaGetSymbolAddress((void**)&rowptr, g_rowptr);
    cudaGetSymbolAddress((void**)&cursor, g_cursor);
    cudaGetSymbolAddress((void**)&partials, g_partials);
    cudaGetSymbolAddress((void**)&csr, g_csr);

    const int TPB = 256;
    const int SCAN_NBLK = (NTOT + 1023) / 1024;   // 440

    // ---- launches 1-5: projection GEMMs (slot 5 = paper proj, for ncu capture) ----
    gemm_proj_tc<<<(N_AUTHOR + 127) / 128, TPB>>>(x_author, wl1_wr, nullptr, h_wr, N_AUTHOR);
    gemm_proj_tc<<<(N_FIELD  + 127) / 128, TPB>>>(x_field,  wl1_rh, nullptr, h_rh, N_FIELD);
    gemm_proj_tc<<<(N_PAPER  + 127) / 128, TPB>>>(x_paper,  wl1_rw, nullptr, h_rw, N_PAPER);
    gemm_proj_tc<<<(N_PAPER  + 127) / 128, TPB>>>(x_paper,  wl1_ht, nullptr, h_ht, N_PAPER);
    gemm_proj_tc<<<(N_PAPER  + 127) / 128, TPB>>>(x_paper,  wl1_ci, nullptr, h_ci, N_PAPER);

    // ---- summed self-weights / biases ----
    wsum3_kernel<<<(F_IN * HID + TPB - 1) / TPB, TPB>>>(wr1_wr, wr1_ci, wr1_rh, wsum1p, F_IN * HID);
    wsum3_kernel<<<1, TPB>>>(b1_wr, b1_ci, b1_rh, bsum1p, HID);
    wsum3_kernel<<<(HID * OUTF + TPB - 1) / TPB, TPB>>>(wr2_wr, wr2_ci, wr2_rh, wsum2, HID * OUTF);
    wsum3_kernel<<<(OUTF + TPB - 1) / TPB, TPB>>>(b2_wr, b2_ci, b2_rh, bsum2, OUTF);

    // ---- layer-1 self terms ----
    gemm_proj_tc<<<(N_PAPER  + 127) / 128, TPB>>>(x_paper,  wsum1p, bsum1p, p1, N_PAPER);
    gemm_proj_tc<<<(N_AUTHOR + 127) / 128, TPB>>>(x_author, wr1_rw, b1_rw,  a1, N_AUTHOR);
    gemm_proj_tc<<<(N_FIELD  + 127) / 128, TPB>>>(x_field,  wr1_ht, b1_ht,  f1, N_FIELD);

    // ---- CSR build: zero counts -> histogram -> scan -> reorder ----
    zero_cnt_kernel<<<(NTOT / 4 + TPB - 1) / TPB, TPB>>>((int4*)cnt, NTOT / 4);
    count_kernel<<<(E_WR + TPB - 1) / TPB, TPB>>>(ei_wr + E_WR, cnt + B_WR, E_WR);
    count_kernel<<<(E_CI + TPB - 1) / TPB, TPB>>>(ei_ci + E_CI, cnt + B_CI, E_CI);
    count_kernel<<<(E_RH + TPB - 1) / TPB, TPB>>>(ei_rh + E_RH, cnt + B_RH, E_RH);
    count_kernel<<<(E_RW + TPB - 1) / TPB, TPB>>>(ei_rw + E_RW, cnt + B_RW, E_RW);
    count_kernel<<<(E_HT + TPB - 1) / TPB, TPB>>>(ei_ht + E_HT, cnt + B_HT, E_HT);

    scan1_kernel<<<SCAN_NBLK, 256>>>(cnt, rowptr, partials);
    scan2_kernel<<<1, 512>>>(partials, SCAN_NBLK);
    scan3_kernel<<<(NTOT + TPB - 1) / TPB, TPB>>>(rowptr, partials, cursor);

    reorder_kernel<<<(E_WR + TPB - 1) / TPB, TPB>>>(ei_wr, E_WR, B_WR, cursor, csr);
    reorder_kernel<<<(E_CI + TPB - 1) / TPB, TPB>>>(ei_ci, E_CI, B_CI, cursor, csr);
    reorder_kernel<<<(E_RH + TPB - 1) / TPB, TPB>>>(ei_rh, E_RH, B_RH, cursor, csr);
    reorder_kernel<<<(E_RW + TPB - 1) / TPB, TPB>>>(ei_rw, E_RW, B_RW, cursor, csr);
    reorder_kernel<<<(E_HT + TPB - 1) / TPB, TPB>>>(ei_ht, E_HT, B_HT, cursor, csr);

    // ---- layer-1 aggregation (fused mean + self + relu), warp per dst ----
    agg_paper_fin<<<(N_PAPER * 32 + TPB - 1) / TPB, TPB>>>(
        (const float2*)h_wr, (const float2*)h_ci, (const float2*)h_rh,
        csr, rowptr, (float2*)p1);
    agg_fin_one<<<(N_AUTHOR * 32 + TPB - 1) / TPB, TPB>>>(
        (const float2*)h_rw, csr, rowptr, B_RW, N_AUTHOR, (float2*)a1);
    agg_fin_one<<<(N_FIELD * 32 + TPB - 1) / TPB, TPB>>>(
        (const float2*)h_ht, csr, rowptr, B_HT, N_FIELD, (float2*)f1);

    // ---- layer-2 aggregation (mean, plain writes; CSR reused) ----
    agg_mean<<<(N_PAPER * 32 + TPB - 1) / TPB, TPB>>>(
        (const float2*)a1, csr, rowptr, B_WR, N_PAPER, (float2*)acc2_wr);
    agg_mean<<<(N_PAPER * 32 + TPB - 1) / TPB, TPB>>>(
        (const float2*)p1, csr, rowptr, B_CI, N_PAPER, (float2*)acc2_ci);
    agg_mean<<<(N_PAPER * 32 + TPB - 1) / TPB, TPB>>>(
        (const float2*)f1, csr, rowptr, B_RH, N_PAPER, (float2*)acc2_rh);

    // ---- fused output GEMM: [100k x 4x64] @ [4x64 x 349] + bias ----
    {
        dim3 grid((N_PAPER + 127) / 128, (OUTF + 63) / 64);
        gemm_out_tc<<<grid, TPB>>>(acc2_wr, acc2_ci, acc2_rh, p1,
                                   wl2_wr, wl2_ci, wl2_rh, wsum2,
                                   bsum2, out, N_PAPER);
    }
}

// round 12
// speedup vs baseline: 2.4932x; 1.1748x over previous
#include <cuda_runtime.h>
#include <cstdint>

// ---------------- problem constants ----------------
#define N_PAPER  100000
#define N_AUTHOR 100000
#define N_FIELD  50000
#define F_IN 128
#define HID  64
#define OUTF 349
#define E_WR 1000000
#define E_RW 1000000
#define E_CI 2000000
#define E_HT 1000000
#define E_RH 1000000
#define E_TOT 6000000

// global (node,type) slot bases for the concatenated CSR
#define B_WR 0          // dst = paper
#define B_CI 100000     // dst = paper
#define B_RH 200000     // dst = paper
#define B_RW 300000     // dst = author
#define B_HT 400000     // dst = field
#define NTOT 450000

// ---------------- scratch (static device memory; no allocs) ----------------
__device__ float g_h_wr[N_AUTHOR * HID];
__device__ float g_h_rw[N_PAPER  * HID];
__device__ float g_h_ci[N_PAPER  * HID];
__device__ float g_h_ht[N_PAPER  * HID];
__device__ float g_h_rh[N_FIELD  * HID];

__device__ float g_p1[N_PAPER  * HID];
__device__ float g_a1[N_AUTHOR * HID];
__device__ float g_f1[N_FIELD  * HID];

__device__ float g_acc2_wr[N_PAPER * HID];
__device__ float g_acc2_ci[N_PAPER * HID];
__device__ float g_acc2_rh[N_PAPER * HID];

__device__ float g_wsum1p[F_IN * HID];
__device__ float g_bsum1p[HID];
__device__ float g_wsum2[HID * OUTF];
__device__ float g_bsum2[OUTF];

__device__ float g_wcat_p[F_IN * 256];   // [wl1_rw | wl1_ci | wl1_ht | wsum1p]
__device__ float g_wcat_a[F_IN * 128];   // [wl1_wr | wr1_rw]
__device__ float g_wcat_f[F_IN * 128];   // [wl1_rh | wr1_ht]

__device__ int g_cnt[NTOT];
__device__ int g_rowptr[NTOT + 1];
__device__ int g_cursor[NTOT];
__device__ int g_partials[512];
__device__ int g_csr[E_TOT];

// ---------------- small helper kernels ----------------

__global__ void zero_cnt_kernel(int4* __restrict__ p, int n4) {
    int idx = blockIdx.x * blockDim.x + threadIdx.x;
    if (idx < n4) p[idx] = make_int4(0, 0, 0, 0);
}

__global__ void wsum3_kernel(const float* __restrict__ w0, const float* __restrict__ w1,
                             const float* __restrict__ w2, float* __restrict__ out, int n) {
    int idx = blockIdx.x * blockDim.x + threadIdx.x;
    if (idx < n) out[idx] = w0[idx] + w1[idx] + w2[idx];
}

// concatenate 8 [128x64] weight blocks into the 3 wcat buffers
__global__ void concat_w(const float* __restrict__ s0, const float* __restrict__ s1,
                         const float* __restrict__ s2, const float* __restrict__ s3,
                         const float* __restrict__ s4, const float* __restrict__ s5,
                         const float* __restrict__ s6, const float* __restrict__ s7,
                         float* __restrict__ wp, float* __restrict__ wa,
                         float* __restrict__ wf) {
    int idx = blockIdx.x * blockDim.x + threadIdx.x;   // 128*512 = 65536 total
    if (idx >= F_IN * 512) return;
    int seg = idx >> 13;          // which [128x64] block
    int e = idx & 8191;
    int k = e >> 6, c = e & 63;
    const float* srcs[8] = {s0, s1, s2, s3, s4, s5, s6, s7};
    float v = srcs[seg][k * 64 + c];
    if (seg < 4)      wp[k * 256 + seg * 64 + c] = v;
    else if (seg < 6) wa[k * 128 + (seg - 4) * 64 + c] = v;
    else              wf[k * 128 + (seg - 6) * 64 + c] = v;
}

__global__ void count_kernel(const int* __restrict__ dst, int* __restrict__ cnt, int E) {
    int idx = blockIdx.x * blockDim.x + threadIdx.x;
    if (idx < E) atomicAdd(&cnt[__ldg(&dst[idx])], 1);
}

// ---- fused exclusive scan over 450k counts (3 kernels) ----
__global__ void scan1_kernel(const int* __restrict__ cnt, int* __restrict__ rp,
                             int* __restrict__ partials) {
    __shared__ int s[256];
    int t = threadIdx.x, b = blockIdx.x;
    int i0 = b * 1024 + t * 4;
    int c0 = (i0     < NTOT) ? cnt[i0]     : 0;
    int c1 = (i0 + 1 < NTOT) ? cnt[i0 + 1] : 0;
    int c2 = (i0 + 2 < NTOT) ? cnt[i0 + 2] : 0;
    int c3 = (i0 + 3 < NTOT) ? cnt[i0 + 3] : 0;
    int ts = c0 + c1 + c2 + c3;
    s[t] = ts;
    __syncthreads();
    for (int off = 1; off < 256; off <<= 1) {
        int v = (t >= off) ? s[t - off] : 0;
        __syncthreads();
        s[t] += v;
        __syncthreads();
    }
    int p = s[t] - ts;
    if (t == 255) partials[b] = s[255];
    if (i0     < NTOT) rp[i0]     = p; p += c0;
    if (i0 + 1 < NTOT) rp[i0 + 1] = p; p += c1;
    if (i0 + 2 < NTOT) rp[i0 + 2] = p; p += c2;
    if (i0 + 3 < NTOT) rp[i0 + 3] = p;
}

__global__ void scan2_kernel(int* __restrict__ partials, int nblk) {
    __shared__ int s[512];
    int t = threadIdx.x;
    int v0 = (t < nblk) ? partials[t] : 0;
    s[t] = v0;
    __syncthreads();
    for (int off = 1; off < 512; off <<= 1) {
        int v = (t >= off) ? s[t - off] : 0;
        __syncthreads();
        s[t] += v;
        __syncthreads();
    }
    if (t < nblk) partials[t] = s[t] - v0;
}

__global__ void scan3_kernel(int* __restrict__ rp, const int* __restrict__ partials,
                             int* __restrict__ cursor) {
    int i = blockIdx.x * blockDim.x + threadIdx.x;
    if (i < NTOT) {
        int v = rp[i] + partials[i >> 10];
        rp[i] = v;
        cursor[i] = v;
    }
    if (i == 0) rp[NTOT] = E_TOT;
}

__global__ void reorder_kernel(const int* __restrict__ ei, int E, int gbase,
                               int* __restrict__ cursor, int* __restrict__ csr) {
    int e = blockIdx.x * blockDim.x + threadIdx.x;
    if (e < E) {
        int s = __ldg(&ei[e]);
        int d = __ldg(&ei[E + e]);
        int pos = atomicAdd(&cursor[gbase + d], 1);
        csr[pos] = s;
    }
}

// ---- CSR-based aggregation: warp per destination, float2 per lane ----

__global__ void agg_paper_fin(const float2* __restrict__ hwr, const float2* __restrict__ hci,
                              const float2* __restrict__ hrh,
                              const int* __restrict__ csr, const int* __restrict__ rp,
                              float2* __restrict__ p) {
    int gw = (blockIdx.x * blockDim.x + threadIdx.x) >> 5;
    int lane = threadIdx.x & 31;
    if (gw >= N_PAPER) return;
    float2 tot = p[gw * 32 + lane];
    const float2* feats[3] = {hwr, hci, hrh};
    #pragma unroll
    for (int t = 0; t < 3; t++) {
        int s = __ldg(&rp[t * 100000 + gw]);
        int e = __ldg(&rp[t * 100000 + gw + 1]);
        float2 acc = make_float2(0.f, 0.f);
        const float2* f = feats[t];
        #pragma unroll 4
        for (int i = s; i < e; i++) {
            int sv = __ldg(&csr[i]);
            float2 v = __ldg(&f[sv * 32 + lane]);
            acc.x += v.x; acc.y += v.y;
        }
        float r = (e > s) ? 1.0f / (float)(e - s) : 0.f;
        tot.x += acc.x * r; tot.y += acc.y * r;
    }
    p[gw * 32 + lane] = make_float2(fmaxf(tot.x, 0.f), fmaxf(tot.y, 0.f));
}

__global__ void agg_fin_one(const float2* __restrict__ feat, const int* __restrict__ csr,
                            const int* __restrict__ rp, int base, int n,
                            float2* __restrict__ y) {
    int gw = (blockIdx.x * blockDim.x + threadIdx.x) >> 5;
    int lane = threadIdx.x & 31;
    if (gw >= n) return;
    int s = __ldg(&rp[base + gw]);
    int e = __ldg(&rp[base + gw + 1]);
    float2 acc = make_float2(0.f, 0.f);
    #pragma unroll 4
    for (int i = s; i < e; i++) {
        int sv = __ldg(&csr[i]);
        float2 v = __ldg(&feat[sv * 32 + lane]);
        acc.x += v.x; acc.y += v.y;
    }
    float r = (e > s) ? 1.0f / (float)(e - s) : 0.f;
    float2 t = y[gw * 32 + lane];
    y[gw * 32 + lane] = make_float2(fmaxf(t.x + acc.x * r, 0.f),
                                    fmaxf(t.y + acc.y * r, 0.f));
}

__global__ void agg_mean(const float2* __restrict__ feat, const int* __restrict__ csr,
                         const int* __restrict__ rp, int base, int n,
                         float2* __restrict__ out) {
    int gw = (blockIdx.x * blockDim.x + threadIdx.x) >> 5;
    int lane = threadIdx.x & 31;
    if (gw >= n) return;
    int s = __ldg(&rp[base + gw]);
    int e = __ldg(&rp[base + gw + 1]);
    float2 acc = make_float2(0.f, 0.f);
    #pragma unroll 4
    for (int i = s; i < e; i++) {
        int sv = __ldg(&csr[i]);
        float2 v = __ldg(&feat[sv * 32 + lane]);
        acc.x += v.x; acc.y += v.y;
    }
    float r = (e > s) ? 1.0f / (float)(e - s) : 0.f;
    out[gw * 32 + lane] = make_float2(acc.x * r, acc.y * r);
}

// ---------------- tf32 tensor-core GEMMs ----------------

__device__ __forceinline__ unsigned f2tf(float f) {
    unsigned u;
    asm("cvt.rna.tf32.f32 %0, %1;" : "=r"(u) : "f"(f));
    return u;
}

__device__ __forceinline__ void mma8(float* c, const unsigned* a, const unsigned* b) {
    asm volatile("mma.sync.aligned.m16n8k8.row.col.f32.tf32.tf32.f32 "
        "{%0,%1,%2,%3}, {%4,%5,%6,%7}, {%8,%9}, {%0,%1,%2,%3};"
        : "+f"(c[0]), "+f"(c[1]), "+f"(c[2]), "+f"(c[3])
        : "r"(a[0]), "r"(a[1]), "r"(a[2]), "r"(a[3]), "r"(b[0]), "r"(b[1]));
}

#define ASTR 36
#define BSTR 72

// Multi-output projection GEMM: C_j[M x 64] = A[M x 128] @ Wcat[:, j*64:(j+1)*64] (+ bias_j)
// grid = (n_tiles, row_blocks); x is fast so tiles sharing an A row-block co-schedule (L2 reuse).
__global__ __launch_bounds__(256) void gemm_proj_multi(
    const float* __restrict__ A, const float* __restrict__ W, int ldw,
    float* o0, float* o1, float* o2, float* o3,
    const float* b0, const float* b1, const float* b2, const float* b3, int M)
{
    __shared__ unsigned As[128][ASTR];
    __shared__ unsigned Ws[32][BSTR];
    const int tid = threadIdx.x;
    const int warp = tid >> 5, lane = tid & 31;
    const int gid = lane >> 2, tig = lane & 3;
    const int wm = (warp & 3) * 32;
    const int wn = (warp >> 2) * 32;
    const int row0 = blockIdx.y * 128;
    const int wc0 = blockIdx.x * 64;

    float* C;
    const float* bias;
    switch (blockIdx.x) {
        case 0: C = o0; bias = b0; break;
        case 1: C = o1; bias = b1; break;
        case 2: C = o2; bias = b2; break;
        default: C = o3; bias = b3; break;
    }

    float acc[2][4][4] = {};

    for (int kk = 0; kk < F_IN; kk += 32) {
        for (int i = tid; i < 128 * 8; i += 256) {
            int r = i >> 3, q = i & 7;
            int rg = row0 + r;
            float4 v = make_float4(0.f, 0.f, 0.f, 0.f);
            if (rg < M) v = *(const float4*)&A[rg * F_IN + kk + q * 4];
            *(uint4*)&As[r][q * 4] = make_uint4(f2tf(v.x), f2tf(v.y), f2tf(v.z), f2tf(v.w));
        }
        for (int i = tid; i < 32 * 16; i += 256) {
            int k = i >> 4, q = i & 15;
            float4 v = *(const float4*)&W[(kk + k) * ldw + wc0 + q * 4];
            *(uint4*)&Ws[k][q * 4] = make_uint4(f2tf(v.x), f2tf(v.y), f2tf(v.z), f2tf(v.w));
        }
        __syncthreads();
        #pragma unroll
        for (int kt = 0; kt < 4; kt++) {
            int k0 = kt * 8;
            unsigned a[2][4], b[4][2];
            #pragma unroll
            for (int mi = 0; mi < 2; mi++) {
                int r = wm + mi * 16 + gid;
                a[mi][0] = As[r][k0 + tig];
                a[mi][1] = As[r + 8][k0 + tig];
                a[mi][2] = As[r][k0 + tig + 4];
                a[mi][3] = As[r + 8][k0 + tig + 4];
            }
            #pragma unroll
            for (int ni = 0; ni < 4; ni++) {
                int n = wn + ni * 8 + gid;
                b[ni][0] = Ws[k0 + tig][n];
                b[ni][1] = Ws[k0 + tig + 4][n];
            }
            #pragma unroll
            for (int mi = 0; mi < 2; mi++)
                #pragma unroll
                for (int ni = 0; ni < 4; ni++)
                    mma8(acc[mi][ni], a[mi], b[ni]);
        }
        __syncthreads();
    }

    #pragma unroll
    for (int ni = 0; ni < 4; ni++) {
        int col = wn + ni * 8 + tig * 2;
        float2 bv = make_float2(0.f, 0.f);
        if (bias) bv = *(const float2*)&bias[col];
        #pragma unroll
        for (int mi = 0; mi < 2; mi++) {
            int r = row0 + wm + mi * 16 + gid;
            if (r < M)
                *(float2*)&C[r * HID + col] =
                    make_float2(acc[mi][ni][0] + bv.x, acc[mi][ni][1] + bv.y);
            if (r + 8 < M)
                *(float2*)&C[(r + 8) * HID + col] =
                    make_float2(acc[mi][ni][2] + bv.x, acc[mi][ni][3] + bv.y);
        }
    }
}

// C[M x 349] = sum_t A_t[M x 64] @ W_t[64 x 349] + bias  (A_t already mean-scaled)
__global__ __launch_bounds__(256) void gemm_out_tc(
    const float* __restrict__ A0, const float* __restrict__ A1,
    const float* __restrict__ A2, const float* __restrict__ A3,
    const float* __restrict__ W0, const float* __restrict__ W1,
    const float* __restrict__ W2, const float* __restrict__ W3,
    const float* __restrict__ bias, float* __restrict__ C, int M)
{
    __shared__ unsigned As[128][ASTR];
    __shared__ unsigned Ws[32][BSTR];
    const int tid = threadIdx.x;
    const int warp = tid >> 5, lane = tid & 31;
    const int gid = lane >> 2, tig = lane & 3;
    const int wm = (warp & 3) * 32;
    const int wn = (warp >> 2) * 32;
    const int row0 = blockIdx.y * 128;
    const int col0 = blockIdx.x * 64;

    const float* Aps[4] = {A0, A1, A2, A3};
    const float* Wps[4] = {W0, W1, W2, W3};

    float acc[2][4][4] = {};

    #pragma unroll 1
    for (int t = 0; t < 4; t++) {
        const float* A = Aps[t];
        const float* W = Wps[t];
        #pragma unroll 1
        for (int kc = 0; kc < HID; kc += 32) {
            for (int i = tid; i < 128 * 8; i += 256) {
                int r = i >> 3, q = i & 7;
                int rg = row0 + r;
                float4 v = make_float4(0.f, 0.f, 0.f, 0.f);
                if (rg < M) v = *(const float4*)&A[rg * HID + kc + q * 4];
                *(uint4*)&As[r][q * 4] = make_uint4(f2tf(v.x), f2tf(v.y), f2tf(v.z), f2tf(v.w));
            }
            for (int i = tid; i < 32 * 64; i += 256) {
                int k = i >> 6, n = i & 63;
                int cg = col0 + n;
                float v = (cg < OUTF) ? W[(kc + k) * OUTF + cg] : 0.f;
                Ws[k][n] = f2tf(v);
            }
            __syncthreads();
            #pragma unroll
            for (int kt = 0; kt < 4; kt++) {
                int k0 = kt * 8;
                unsigned a[2][4], b[4][2];
                #pragma unroll
                for (int mi = 0; mi < 2; mi++) {
                    int r = wm + mi * 16 + gid;
                    a[mi][0] = As[r][k0 + tig];
                    a[mi][1] = As[r + 8][k0 + tig];
                    a[mi][2] = As[r][k0 + tig + 4];
                    a[mi][3] = As[r + 8][k0 + tig + 4];
                }
                #pragma unroll
                for (int ni = 0; ni < 4; ni++) {
                    int n = wn + ni * 8 + gid;
                    b[ni][0] = Ws[k0 + tig][n];
                    b[ni][1] = Ws[k0 + tig + 4][n];
                }
                #pragma unroll
                for (int mi = 0; mi < 2; mi++)
                    #pragma unroll
                    for (int ni = 0; ni < 4; ni++)
                        mma8(acc[mi][ni], a[mi], b[ni]);
            }
            __syncthreads();
        }
    }

    #pragma unroll
    for (int ni = 0; ni < 4; ni++) {
        int col = col0 + wn + ni * 8 + tig * 2;
        float b0v = (col < OUTF) ? bias[col] : 0.f;
        float b1v = (col + 1 < OUTF) ? bias[col + 1] : 0.f;
        #pragma unroll
        for (int mi = 0; mi < 2; mi++) {
            int r = row0 + wm + mi * 16 + gid;
            if (r < M) {
                if (col < OUTF)     C[r * OUTF + col]     = acc[mi][ni][0] + b0v;
                if (col + 1 < OUTF) C[r * OUTF + col + 1] = acc[mi][ni][1] + b1v;
            }
            int r2 = r + 8;
            if (r2 < M) {
                if (col < OUTF)     C[r2 * OUTF + col]     = acc[mi][ni][2] + b0v;
                if (col + 1 < OUTF) C[r2 * OUTF + col + 1] = acc[mi][ni][3] + b1v;
            }
        }
    }
}

// ---------------- host launcher ----------------
extern "C" void kernel_launch(void* const* d_in, const int* in_sizes, int n_in,
                              void* d_out, int out_size) {
    (void)in_sizes; (void)n_in; (void)out_size;
    const float* x_paper  = (const float*)d_in[0];
    const float* x_author = (const float*)d_in[1];
    const float* x_field  = (const float*)d_in[2];
    const int* ei_wr = (const int*)d_in[3];
    const int* ei_rw = (const int*)d_in[4];
    const int* ei_ci = (const int*)d_in[5];
    const int* ei_ht = (const int*)d_in[6];
    const int* ei_rh = (const int*)d_in[7];
    const float* wl1_wr = (const float*)d_in[8];
    const float* wr1_wr = (const float*)d_in[9];
    const float* b1_wr  = (const float*)d_in[10];
    const float* wl1_rw = (const float*)d_in[11];
    const float* wr1_rw = (const float*)d_in[12];
    const float* b1_rw  = (const float*)d_in[13];
    const float* wl1_ci = (const float*)d_in[14];
    const float* wr1_ci = (const float*)d_in[15];
    const float* b1_ci  = (const float*)d_in[16];
    const float* wl1_ht = (const float*)d_in[17];
    const float* wr1_ht = (const float*)d_in[18];
    const float* b1_ht  = (const float*)d_in[19];
    const float* wl1_rh = (const float*)d_in[20];
    const float* wr1_rh = (const float*)d_in[21];
    const float* b1_rh  = (const float*)d_in[22];
    const float* wl2_wr = (const float*)d_in[23];
    const float* wr2_wr = (const float*)d_in[24];
    const float* b2_wr  = (const float*)d_in[25];
    const float* wl2_ci = (const float*)d_in[26];
    const float* wr2_ci = (const float*)d_in[27];
    const float* b2_ci  = (const float*)d_in[28];
    const float* wl2_rh = (const float*)d_in[29];
    const float* wr2_rh = (const float*)d_in[30];
    const float* b2_rh  = (const float*)d_in[31];
    float* out = (float*)d_out;

    float *h_wr, *h_rw, *h_ci, *h_ht, *h_rh, *p1, *a1, *f1;
    float *acc2_wr, *acc2_ci, *acc2_rh;
    float *wsum1p, *bsum1p, *wsum2, *bsum2;
    float *wcat_p, *wcat_a, *wcat_f;
    int *cnt, *rowptr, *cursor, *partials, *csr;
    cudaGetSymbolAddress((void**)&h_wr, g_h_wr);
    cudaGetSymbolAddress((void**)&h_rw, g_h_rw);
    cudaGetSymbolAddress((void**)&h_ci, g_h_ci);
    cudaGetSymbolAddress((void**)&h_ht, g_h_ht);
    cudaGetSymbolAddress((void**)&h_rh, g_h_rh);
    cudaGetSymbolAddress((void**)&p1, g_p1);
    cudaGetSymbolAddress((void**)&a1, g_a1);
    cudaGetSymbolAddress((void**)&f1, g_f1);
    cudaGetSymbolAddress((void**)&acc2_wr, g_acc2_wr);
    cudaGetSymbolAddress((void**)&acc2_ci, g_acc2_ci);
    cudaGetSymbolAddress((void**)&acc2_rh, g_acc2_rh);
    cudaGetSymbolAddress((void**)&wsum1p, g_wsum1p);
    cudaGetSymbolAddress((void**)&bsum1p, g_bsum1p);
    cudaGetSymbolAddress((void**)&wsum2, g_wsum2);
    cudaGetSymbolAddress((void**)&bsum2, g_bsum2);
    cudaGetSymbolAddress((void**)&wcat_p, g_wcat_p);
    cudaGetSymbolAddress((void**)&wcat_a, g_wcat_a);
    cudaGetSymbolAddress((void**)&wcat_f, g_wcat_f);
    cudaGetSymbolAddress((void**)&cnt, g_cnt);
    cudaGetSymbolAddress((void**)&rowptr, g_rowptr);
    cudaGetSymbolAddress((void**)&cursor, g_cursor);
    cudaGetSymbolAddress((void**)&partials, g_partials);
    cudaGetSymbolAddress((void**)&csr, g_csr);

    const int TPB = 256;
    const int SCAN_NBLK = (NTOT + 1023) / 1024;   // 440

    // ---- summed self-weights / biases (needed before concat) ----
    wsum3_kernel<<<(F_IN * HID + TPB - 1) / TPB, TPB>>>(wr1_wr, wr1_ci, wr1_rh, wsum1p, F_IN * HID);
    wsum3_kernel<<<1, TPB>>>(b1_wr, b1_ci, b1_rh, bsum1p, HID);
    wsum3_kernel<<<(HID * OUTF + TPB - 1) / TPB, TPB>>>(wr2_wr, wr2_ci, wr2_rh, wsum2, HID * OUTF);
    wsum3_kernel<<<(OUTF + TPB - 1) / TPB, TPB>>>(b2_wr, b2_ci, b2_rh, bsum2, OUTF);

    // ---- concat weights for fused projections ----
    concat_w<<<(F_IN * 512 + TPB - 1) / TPB, TPB>>>(
        wl1_rw, wl1_ci, wl1_ht, wsum1p,      // paper tiles 0-3
        wl1_wr, wr1_rw,                      // author tiles 0-1
        wl1_rh, wr1_ht,                      // field tiles 0-1
        wcat_p, wcat_a, wcat_f);

    // ---- fused layer-1 projections (3 launches; launch idx 5 = paper) ----
    {
        dim3 gp(4, (N_PAPER + 127) / 128);
        gemm_proj_multi<<<gp, TPB>>>(x_paper, wcat_p, 256,
                                     h_rw, h_ci, h_ht, p1,
                                     nullptr, nullptr, nullptr, bsum1p, N_PAPER);
        dim3 ga(2, (N_AUTHOR + 127) / 128);
        gemm_proj_multi<<<ga, TPB>>>(x_author, wcat_a, 128,
                                     h_wr, a1, nullptr, nullptr,
                                     nullptr, b1_rw, nullptr, nullptr, N_AUTHOR);
        dim3 gf(2, (N_FIELD + 127) / 128);
        gemm_proj_multi<<<gf, TPB>>>(x_field, wcat_f, 128,
                                     h_rh, f1, nullptr, nullptr,
                                     nullptr, b1_ht, nullptr, nullptr, N_FIELD);
    }

    // ---- CSR build: zero counts -> histogram -> scan -> reorder ----
    zero_cnt_kernel<<<(NTOT / 4 + TPB - 1) / TPB, TPB>>>((int4*)cnt, NTOT / 4);
    count_kernel<<<(E_WR + TPB - 1) / TPB, TPB>>>(ei_wr + E_WR, cnt + B_WR, E_WR);
    count_kernel<<<(E_CI + TPB - 1) / TPB, TPB>>>(ei_ci + E_CI, cnt + B_CI, E_CI);
    count_kernel<<<(E_RH + TPB - 1) / TPB, TPB>>>(ei_rh + E_RH, cnt + B_RH, E_RH);
    count_kernel<<<(E_RW + TPB - 1) / TPB, TPB>>>(ei_rw + E_RW, cnt + B_RW, E_RW);
    count_kernel<<<(E_HT + TPB - 1) / TPB, TPB>>>(ei_ht + E_HT, cnt + B_HT, E_HT);

    scan1_kernel<<<SCAN_NBLK, 256>>>(cnt, rowptr, partials);
    scan2_kernel<<<1, 512>>>(partials, SCAN_NBLK);
    scan3_kernel<<<(NTOT + TPB - 1) / TPB, TPB>>>(rowptr, partials, cursor);

    reorder_kernel<<<(E_WR + TPB - 1) / TPB, TPB>>>(ei_wr, E_WR, B_WR, cursor, csr);
    reorder_kernel<<<(E_CI + TPB - 1) / TPB, TPB>>>(ei_ci, E_CI, B_CI, cursor, csr);
    reorder_kernel<<<(E_RH + TPB - 1) / TPB, TPB>>>(ei_rh, E_RH, B_RH, cursor, csr);
    reorder_kernel<<<(E_RW + TPB - 1) / TPB, TPB>>>(ei_rw, E_RW, B_RW, cursor, csr);
    reorder_kernel<<<(E_HT + TPB - 1) / TPB, TPB>>>(ei_ht, E_HT, B_HT, cursor, csr);

    // ---- layer-1 aggregation (fused mean + self + relu), warp per dst ----
    agg_paper_fin<<<(N_PAPER * 32 + TPB - 1) / TPB, TPB>>>(
        (const float2*)h_wr, (const float2*)h_ci, (const float2*)h_rh,
        csr, rowptr, (float2*)p1);
    agg_fin_one<<<(N_AUTHOR * 32 + TPB - 1) / TPB, TPB>>>(
        (const float2*)h_rw, csr, rowptr, B_RW, N_AUTHOR, (float2*)a1);
    agg_fin_one<<<(N_FIELD * 32 + TPB - 1) / TPB, TPB>>>(
        (const float2*)h_ht, csr, rowptr, B_HT, N_FIELD, (float2*)f1);

    // ---- layer-2 aggregation (mean, plain writes; CSR reused) ----
    agg_mean<<<(N_PAPER * 32 + TPB - 1) / TPB, TPB>>>(
        (const float2*)a1, csr, rowptr, B_WR, N_PAPER, (float2*)acc2_wr);
    agg_mean<<<(N_PAPER * 32 + TPB - 1) / TPB, TPB>>>(
        (const float2*)p1, csr, rowptr, B_CI, N_PAPER, (float2*)acc2_ci);
    agg_mean<<<(N_PAPER * 32 + TPB - 1) / TPB, TPB>>>(
        (const float2*)f1, csr, rowptr, B_RH, N_PAPER, (float2*)acc2_rh);

    // ---- fused output GEMM: [100k x 4x64] @ [4x64 x 349] + bias ----
    {
        dim3 grid((OUTF + 63) / 64, (N_PAPER + 127) / 128);
        gemm_out_tc<<<grid, TPB>>>(acc2_wr, acc2_ci, acc2_rh, p1,
                                   wl2_wr, wl2_ci, wl2_rh, wsum2,
                                   bsum2, out, N_PAPER);
    }
}

// round 13
// speedup vs baseline: 2.5791x; 1.0345x over previous
#include <cuda_runtime.h>
#include <cuda_fp16.h>
#include <cstdint>

// ---------------- problem constants ----------------
#define N_PAPER  100000
#define N_AUTHOR 100000
#define N_FIELD  50000
#define F_IN 128
#define HID  64
#define OUTF 349
#define E_WR 1000000
#define E_RW 1000000
#define E_CI 2000000
#define E_HT 1000000
#define E_RH 1000000
#define E_TOT 6000000

// global (node,type) slot bases for the concatenated CSR
#define B_WR 0          // dst = paper
#define B_CI 100000     // dst = paper
#define B_RH 200000     // dst = paper
#define B_RW 300000     // dst = author
#define B_HT 400000     // dst = field
#define NTOT 450000

// ---------------- scratch (static device memory; no allocs) ----------------
// fp16 feature buffers (aggregation operands + GEMM A operands)
__device__ __half g_h_wr[N_AUTHOR * HID];
__device__ __half g_h_rw[N_PAPER  * HID];
__device__ __half g_h_ci[N_PAPER  * HID];
__device__ __half g_h_ht[N_PAPER  * HID];
__device__ __half g_h_rh[N_FIELD  * HID];

__device__ __half g_p1[N_PAPER  * HID];
__device__ __half g_a1[N_AUTHOR * HID];
__device__ __half g_f1[N_FIELD  * HID];

__device__ __half g_acc2_wr[N_PAPER * HID];
__device__ __half g_acc2_ci[N_PAPER * HID];
__device__ __half g_acc2_rh[N_PAPER * HID];

__device__ float g_wsum1p[F_IN * HID];
__device__ float g_bsum1p[HID];
__device__ float g_wsum2[HID * OUTF];
__device__ float g_bsum2[OUTF];

__device__ float g_wcat_p[F_IN * 256];   // [wl1_rw | wl1_ci | wl1_ht | wsum1p]
__device__ float g_wcat_a[F_IN * 128];   // [wl1_wr | wr1_rw]
__device__ float g_wcat_f[F_IN * 128];   // [wl1_rh | wr1_ht]

__device__ int g_cnt[NTOT];
__device__ int g_rowptr[NTOT + 1];
__device__ int g_cursor[NTOT];
__device__ int g_partials[512];
__device__ int g_csr[E_TOT];

// ---------------- small helper kernels ----------------

__global__ void zero_cnt_kernel(int4* __restrict__ p, int n4) {
    int idx = blockIdx.x * blockDim.x + threadIdx.x;
    if (idx < n4) p[idx] = make_int4(0, 0, 0, 0);
}

__global__ void wsum3_kernel(const float* __restrict__ w0, const float* __restrict__ w1,
                             const float* __restrict__ w2, float* __restrict__ out, int n) {
    int idx = blockIdx.x * blockDim.x + threadIdx.x;
    if (idx < n) out[idx] = w0[idx] + w1[idx] + w2[idx];
}

// concatenate 8 [128x64] weight blocks into the 3 wcat buffers
__global__ void concat_w(const float* __restrict__ s0, const float* __restrict__ s1,
                         const float* __restrict__ s2, const float* __restrict__ s3,
                         const float* __restrict__ s4, const float* __restrict__ s5,
                         const float* __restrict__ s6, const float* __restrict__ s7,
                         float* __restrict__ wp, float* __restrict__ wa,
                         float* __restrict__ wf) {
    int idx = blockIdx.x * blockDim.x + threadIdx.x;   // 128*512 = 65536 total
    if (idx >= F_IN * 512) return;
    int seg = idx >> 13;
    int e = idx & 8191;
    int k = e >> 6, c = e & 63;
    const float* srcs[8] = {s0, s1, s2, s3, s4, s5, s6, s7};
    float v = srcs[seg][k * 64 + c];
    if (seg < 4)      wp[k * 256 + seg * 64 + c] = v;
    else if (seg < 6) wa[k * 128 + (seg - 4) * 64 + c] = v;
    else              wf[k * 128 + (seg - 6) * 64 + c] = v;
}

__global__ void count_kernel(const int* __restrict__ dst, int* __restrict__ cnt, int E) {
    int idx = blockIdx.x * blockDim.x + threadIdx.x;
    if (idx < E) atomicAdd(&cnt[__ldg(&dst[idx])], 1);
}

// ---- fused exclusive scan over 450k counts (3 kernels) ----
__global__ void scan1_kernel(const int* __restrict__ cnt, int* __restrict__ rp,
                             int* __restrict__ partials) {
    __shared__ int s[256];
    int t = threadIdx.x, b = blockIdx.x;
    int i0 = b * 1024 + t * 4;
    int c0 = (i0     < NTOT) ? cnt[i0]     : 0;
    int c1 = (i0 + 1 < NTOT) ? cnt[i0 + 1] : 0;
    int c2 = (i0 + 2 < NTOT) ? cnt[i0 + 2] : 0;
    int c3 = (i0 + 3 < NTOT) ? cnt[i0 + 3] : 0;
    int ts = c0 + c1 + c2 + c3;
    s[t] = ts;
    __syncthreads();
    for (int off = 1; off < 256; off <<= 1) {
        int v = (t >= off) ? s[t - off] : 0;
        __syncthreads();
        s[t] += v;
        __syncthreads();
    }
    int p = s[t] - ts;
    if (t == 255) partials[b] = s[255];
    if (i0     < NTOT) rp[i0]     = p; p += c0;
    if (i0 + 1 < NTOT) rp[i0 + 1] = p; p += c1;
    if (i0 + 2 < NTOT) rp[i0 + 2] = p; p += c2;
    if (i0 + 3 < NTOT) rp[i0 + 3] = p;
}

__global__ void scan2_kernel(int* __restrict__ partials, int nblk) {
    __shared__ int s[512];
    int t = threadIdx.x;
    int v0 = (t < nblk) ? partials[t] : 0;
    s[t] = v0;
    __syncthreads();
    for (int off = 1; off < 512; off <<= 1) {
        int v = (t >= off) ? s[t - off] : 0;
        __syncthreads();
        s[t] += v;
        __syncthreads();
    }
    if (t < nblk) partials[t] = s[t] - v0;
}

__global__ void scan3_kernel(int* __restrict__ rp, const int* __restrict__ partials,
                             int* __restrict__ cursor) {
    int i = blockIdx.x * blockDim.x + threadIdx.x;
    if (i < NTOT) {
        int v = rp[i] + partials[i >> 10];
        rp[i] = v;
        cursor[i] = v;
    }
    if (i == 0) rp[NTOT] = E_TOT;
}

__global__ void reorder_kernel(const int* __restrict__ ei, int E, int gbase,
                               int* __restrict__ cursor, int* __restrict__ csr) {
    int e = blockIdx.x * blockDim.x + threadIdx.x;
    if (e < E) {
        int s = __ldg(&ei[e]);
        int d = __ldg(&ei[E + e]);
        int pos = atomicAdd(&cursor[gbase + d], 1);
        csr[pos] = s;
    }
}

// ---- CSR-based aggregation: warp per destination, half2 per lane, fp32 accum ----

__device__ __forceinline__ float2 h2f(__half2 h) { return __half22float2(h); }
__device__ __forceinline__ __half2 f2h(float x, float y) {
    return __floats2half2_rn(x, y);
}

// paper layer-1, fully fused: p = relu(p_self + mean_wr + mean_ci + mean_rh)
__global__ void agg_paper_fin(const __half2* __restrict__ hwr, const __half2* __restrict__ hci,
                              const __half2* __restrict__ hrh,
                              const int* __restrict__ csr, const int* __restrict__ rp,
                              __half2* __restrict__ p) {
    int gw = (blockIdx.x * blockDim.x + threadIdx.x) >> 5;
    int lane = threadIdx.x & 31;
    if (gw >= N_PAPER) return;
    float2 tot = h2f(p[gw * 32 + lane]);
    const __half2* feats[3] = {hwr, hci, hrh};
    #pragma unroll
    for (int t = 0; t < 3; t++) {
        int s = __ldg(&rp[t * 100000 + gw]);
        int e = __ldg(&rp[t * 100000 + gw + 1]);
        float2 acc = make_float2(0.f, 0.f);
        const __half2* f = feats[t];
        #pragma unroll 4
        for (int i = s; i < e; i++) {
            int sv = __ldg(&csr[i]);
            float2 v = h2f(__ldg(&f[sv * 32 + lane]));
            acc.x += v.x; acc.y += v.y;
        }
        float r = (e > s) ? 1.0f / (float)(e - s) : 0.f;
        tot.x += acc.x * r; tot.y += acc.y * r;
    }
    p[gw * 32 + lane] = f2h(fmaxf(tot.x, 0.f), fmaxf(tot.y, 0.f));
}

// y = relu(y + mean over one segment)
__global__ void agg_fin_one(const __half2* __restrict__ feat, const int* __restrict__ csr,
                            const int* __restrict__ rp, int base, int n,
                            __half2* __restrict__ y) {
    int gw = (blockIdx.x * blockDim.x + threadIdx.x) >> 5;
    int lane = threadIdx.x & 31;
    if (gw >= n) return;
    int s = __ldg(&rp[base + gw]);
    int e = __ldg(&rp[base + gw + 1]);
    float2 acc = make_float2(0.f, 0.f);
    #pragma unroll 4
    for (int i = s; i < e; i++) {
        int sv = __ldg(&csr[i]);
        float2 v = h2f(__ldg(&feat[sv * 32 + lane]));
        acc.x += v.x; acc.y += v.y;
    }
    float r = (e > s) ? 1.0f / (float)(e - s) : 0.f;
    float2 t = h2f(y[gw * 32 + lane]);
    y[gw * 32 + lane] = f2h(fmaxf(t.x + acc.x * r, 0.f), fmaxf(t.y + acc.y * r, 0.f));
}

// layer-2: all three paper means in ONE launch; warp gw in [0, 3*N_PAPER)
__global__ void agg_mean3(const __half2* __restrict__ fa, const __half2* __restrict__ fp,
                          const __half2* __restrict__ ff,
                          const int* __restrict__ csr, const int* __restrict__ rp,
                          __half2* __restrict__ oa, __half2* __restrict__ op,
                          __half2* __restrict__ of) {
    int gw = (blockIdx.x * blockDim.x + threadIdx.x) >> 5;
    int lane = threadIdx.x & 31;
    if (gw >= 3 * N_PAPER) return;
    int t = gw / N_PAPER;            // 0=wr(a1), 1=ci(p1), 2=rh(f1)
    int node = gw - t * N_PAPER;
    const __half2* f = (t == 0) ? fa : (t == 1) ? fp : ff;
    __half2* o       = (t == 0) ? oa : (t == 1) ? op : of;
    int base = t * 100000;           // B_WR, B_CI, B_RH
    int s = __ldg(&rp[base + node]);
    int e = __ldg(&rp[base + node + 1]);
    float2 acc = make_float2(0.f, 0.f);
    #pragma unroll 4
    for (int i = s; i < e; i++) {
        int sv = __ldg(&csr[i]);
        float2 v = h2f(__ldg(&f[sv * 32 + lane]));
        acc.x += v.x; acc.y += v.y;
    }
    float r = (e > s) ? 1.0f / (float)(e - s) : 0.f;
    o[node * 32 + lane] = f2h(acc.x * r, acc.y * r);
}

// ---------------- tf32 tensor-core GEMMs ----------------

__device__ __forceinline__ unsigned f2tf(float f) {
    unsigned u;
    asm("cvt.rna.tf32.f32 %0, %1;" : "=r"(u) : "f"(f));
    return u;
}

__device__ __forceinline__ void mma8(float* c, const unsigned* a, const unsigned* b) {
    asm volatile("mma.sync.aligned.m16n8k8.row.col.f32.tf32.tf32.f32 "
        "{%0,%1,%2,%3}, {%4,%5,%6,%7}, {%8,%9}, {%0,%1,%2,%3};"
        : "+f"(c[0]), "+f"(c[1]), "+f"(c[2]), "+f"(c[3])
        : "r"(a[0]), "r"(a[1]), "r"(a[2]), "r"(a[3]), "r"(b[0]), "r"(b[1]));
}

#define ASTR 36
#define BSTR 72

// Multi-output projection GEMM: C_j[M x 64] = A[M x 128] @ Wcat[:, j*64:(j+1)*64] (+ bias_j)
// fp32 A/W in, fp16 out. grid = (n_tiles, row_blocks), x fast for A L2 reuse.
__global__ __launch_bounds__(256) void gemm_proj_multi(
    const float* __restrict__ A, const float* __restrict__ W, int ldw,
    __half* o0, __half* o1, __half* o2, __half* o3,
    const float* b0, const float* b1, const float* b2, const float* b3, int M)
{
    __shared__ unsigned As[128][ASTR];
    __shared__ unsigned Ws[32][BSTR];
    const int tid = threadIdx.x;
    const int warp = tid >> 5, lane = tid & 31;
    const int gid = lane >> 2, tig = lane & 3;
    const int wm = (warp & 3) * 32;
    const int wn = (warp >> 2) * 32;
    const int row0 = blockIdx.y * 128;
    const int wc0 = blockIdx.x * 64;

    __half* C;
    const float* bias;
    switch (blockIdx.x) {
        case 0: C = o0; bias = b0; break;
        case 1: C = o1; bias = b1; break;
        case 2: C = o2; bias = b2; break;
        default: C = o3; bias = b3; break;
    }

    float acc[2][4][4] = {};

    for (int kk = 0; kk < F_IN; kk += 32) {
        for (int i = tid; i < 128 * 8; i += 256) {
            int r = i >> 3, q = i & 7;
            int rg = row0 + r;
            float4 v = make_float4(0.f, 0.f, 0.f, 0.f);
            if (rg < M) v = *(const float4*)&A[rg * F_IN + kk + q * 4];
            *(uint4*)&As[r][q * 4] = make_uint4(f2tf(v.x), f2tf(v.y), f2tf(v.z), f2tf(v.w));
        }
        for (int i = tid; i < 32 * 16; i += 256) {
            int k = i >> 4, q = i & 15;
            float4 v = *(const float4*)&W[(kk + k) * ldw + wc0 + q * 4];
            *(uint4*)&Ws[k][q * 4] = make_uint4(f2tf(v.x), f2tf(v.y), f2tf(v.z), f2tf(v.w));
        }
        __syncthreads();
        #pragma unroll
        for (int kt = 0; kt < 4; kt++) {
            int k0 = kt * 8;
            unsigned a[2][4], b[4][2];
            #pragma unroll
            for (int mi = 0; mi < 2; mi++) {
                int r = wm + mi * 16 + gid;
                a[mi][0] = As[r][k0 + tig];
                a[mi][1] = As[r + 8][k0 + tig];
                a[mi][2] = As[r][k0 + tig + 4];
                a[mi][3] = As[r + 8][k0 + tig + 4];
            }
            #pragma unroll
            for (int ni = 0; ni < 4; ni++) {
                int n = wn + ni * 8 + gid;
                b[ni][0] = Ws[k0 + tig][n];
                b[ni][1] = Ws[k0 + tig + 4][n];
            }
            #pragma unroll
            for (int mi = 0; mi < 2; mi++)
                #pragma unroll
                for (int ni = 0; ni < 4; ni++)
                    mma8(acc[mi][ni], a[mi], b[ni]);
        }
        __syncthreads();
    }

    #pragma unroll
    for (int ni = 0; ni < 4; ni++) {
        int col = wn + ni * 8 + tig * 2;
        float2 bv = make_float2(0.f, 0.f);
        if (bias) bv = *(const float2*)&bias[col];
        #pragma unroll
        for (int mi = 0; mi < 2; mi++) {
            int r = row0 + wm + mi * 16 + gid;
            if (r < M)
                *(__half2*)&C[r * HID + col] =
                    __floats2half2_rn(acc[mi][ni][0] + bv.x, acc[mi][ni][1] + bv.y);
            if (r + 8 < M)
                *(__half2*)&C[(r + 8) * HID + col] =
                    __floats2half2_rn(acc[mi][ni][2] + bv.x, acc[mi][ni][3] + bv.y);
        }
    }
}

// C[M x 349] = sum_t A_t[M x 64] @ W_t[64 x 349] + bias  (A_t fp16, already mean-scaled)
__global__ __launch_bounds__(256) void gemm_out_tc(
    const __half* __restrict__ A0, const __half* __restrict__ A1,
    const __half* __restrict__ A2, const __half* __restrict__ A3,
    const float* __restrict__ W0, const float* __restrict__ W1,
    const float* __restrict__ W2, const float* __restrict__ W3,
    const float* __restrict__ bias, float* __restrict__ C, int M)
{
    __shared__ unsigned As[128][ASTR];
    __shared__ unsigned Ws[32][BSTR];
    const int tid = threadIdx.x;
    const int warp = tid >> 5, lane = tid & 31;
    const int gid = lane >> 2, tig = lane & 3;
    const int wm = (warp & 3) * 32;
    const int wn = (warp >> 2) * 32;
    const int row0 = blockIdx.y * 128;
    const int col0 = blockIdx.x * 64;

    const __half* Aps[4] = {A0, A1, A2, A3};
    const float* Wps[4] = {W0, W1, W2, W3};

    float acc[2][4][4] = {};

    #pragma unroll 1
    for (int t = 0; t < 4; t++) {
        const __half* A = Aps[t];
        const float* W = Wps[t];
        #pragma unroll 1
        for (int kc = 0; kc < HID; kc += 32) {
            for (int i = tid; i < 128 * 8; i += 256) {
                int r = i >> 3, q = i & 7;
                int rg = row0 + r;
                float2 v01 = make_float2(0.f, 0.f), v23 = make_float2(0.f, 0.f);
                if (rg < M) {
                    __half2 h0 = *(const __half2*)&A[rg * HID + kc + q * 4];
                    __half2 h1 = *(const __half2*)&A[rg * HID + kc + q * 4 + 2];
                    v01 = __half22float2(h0);
                    v23 = __half22float2(h1);
                }
                *(uint4*)&As[r][q * 4] =
                    make_uint4(f2tf(v01.x), f2tf(v01.y), f2tf(v23.x), f2tf(v23.y));
            }
            for (int i = tid; i < 32 * 64; i += 256) {
                int k = i >> 6, n = i & 63;
                int cg = col0 + n;
                float v = (cg < OUTF) ? W[(kc + k) * OUTF + cg] : 0.f;
                Ws[k][n] = f2tf(v);
            }
            __syncthreads();
            #pragma unroll
            for (int kt = 0; kt < 4; kt++) {
                int k0 = kt * 8;
                unsigned a[2][4], b[4][2];
                #pragma unroll
                for (int mi = 0; mi < 2; mi++) {
                    int r = wm + mi * 16 + gid;
                    a[mi][0] = As[r][k0 + tig];
                    a[mi][1] = As[r + 8][k0 + tig];
                    a[mi][2] = As[r][k0 + tig + 4];
                    a[mi][3] = As[r + 8][k0 + tig + 4];
                }
                #pragma unroll
                for (int ni = 0; ni < 4; ni++) {
                    int n = wn + ni * 8 + gid;
                    b[ni][0] = Ws[k0 + tig][n];
                    b[ni][1] = Ws[k0 + tig + 4][n];
                }
                #pragma unroll
                for (int mi = 0; mi < 2; mi++)
                    #pragma unroll
                    for (int ni = 0; ni < 4; ni++)
                        mma8(acc[mi][ni], a[mi], b[ni]);
            }
            __syncthreads();
        }
    }

    #pragma unroll
    for (int ni = 0; ni < 4; ni++) {
        int col = col0 + wn + ni * 8 + tig * 2;
        float b0v = (col < OUTF) ? bias[col] : 0.f;
        float b1v = (col + 1 < OUTF) ? bias[col + 1] : 0.f;
        #pragma unroll
        for (int mi = 0; mi < 2; mi++) {
            int r = row0 + wm + mi * 16 + gid;
            if (r < M) {
                if (col < OUTF)     C[r * OUTF + col]     = acc[mi][ni][0] + b0v;
                if (col + 1 < OUTF) C[r * OUTF + col + 1] = acc[mi][ni][1] + b1v;
            }
            int r2 = r + 8;
            if (r2 < M) {
                if (col < OUTF)     C[r2 * OUTF + col]     = acc[mi][ni][2] + b0v;
                if (col + 1 < OUTF) C[r2 * OUTF + col + 1] = acc[mi][ni][3] + b1v;
            }
        }
    }
}

// ---------------- host launcher ----------------
extern "C" void kernel_launch(void* const* d_in, const int* in_sizes, int n_in,
                              void* d_out, int out_size) {
    (void)in_sizes; (void)n_in; (void)out_size;
    const float* x_paper  = (const float*)d_in[0];
    const float* x_author = (const float*)d_in[1];
    const float* x_field  = (const float*)d_in[2];
    const int* ei_wr = (const int*)d_in[3];
    const int* ei_rw = (const int*)d_in[4];
    const int* ei_ci = (const int*)d_in[5];
    const int* ei_ht = (const int*)d_in[6];
    const int* ei_rh = (const int*)d_in[7];
    const float* wl1_wr = (const float*)d_in[8];
    const float* wr1_wr = (const float*)d_in[9];
    const float* b1_wr  = (const float*)d_in[10];
    const float* wl1_rw = (const float*)d_in[11];
    const float* wr1_rw = (const float*)d_in[12];
    const float* b1_rw  = (const float*)d_in[13];
    const float* wl1_ci = (const float*)d_in[14];
    const float* wr1_ci = (const float*)d_in[15];
    const float* b1_ci  = (const float*)d_in[16];
    const float* wl1_ht = (const float*)d_in[17];
    const float* wr1_ht = (const float*)d_in[18];
    const float* b1_ht  = (const float*)d_in[19];
    const float* wl1_rh = (const float*)d_in[20];
    const float* wr1_rh = (const float*)d_in[21];
    const float* b1_rh  = (const float*)d_in[22];
    const float* wl2_wr = (const float*)d_in[23];
    const float* wr2_wr = (const float*)d_in[24];
    const float* b2_wr  = (const float*)d_in[25];
    const float* wl2_ci = (const float*)d_in[26];
    const float* wr2_ci = (const float*)d_in[27];
    const float* b2_ci  = (const float*)d_in[28];
    const float* wl2_rh = (const float*)d_in[29];
    const float* wr2_rh = (const float*)d_in[30];
    const float* b2_rh  = (const float*)d_in[31];
    float* out = (float*)d_out;

    __half *h_wr, *h_rw, *h_ci, *h_ht, *h_rh, *p1, *a1, *f1;
    __half *acc2_wr, *acc2_ci, *acc2_rh;
    float *wsum1p, *bsum1p, *wsum2, *bsum2;
    float *wcat_p, *wcat_a, *wcat_f;
    int *cnt, *rowptr, *cursor, *partials, *csr;
    cudaGetSymbolAddress((void**)&h_wr, g_h_wr);
    cudaGetSymbolAddress((void**)&h_rw, g_h_rw);
    cudaGetSymbolAddress((void**)&h_ci, g_h_ci);
    cudaGetSymbolAddress((void**)&h_ht, g_h_ht);
    cudaGetSymbolAddress((void**)&h_rh, g_h_rh);
    cudaGetSymbolAddress((void**)&p1, g_p1);
    cudaGetSymbolAddress((void**)&a1, g_a1);
    cudaGetSymbolAddress((void**)&f1, g_f1);
    cudaGetSymbolAddress((void**)&acc2_wr, g_acc2_wr);
    cudaGetSymbolAddress((void**)&acc2_ci, g_acc2_ci);
    cudaGetSymbolAddress((void**)&acc2_rh, g_acc2_rh);
    cudaGetSymbolAddress((void**)&wsum1p, g_wsum1p);
    cudaGetSymbolAddress((void**)&bsum1p, g_bsum1p);
    cudaGetSymbolAddress((void**)&wsum2, g_wsum2);
    cudaGetSymbolAddress((void**)&bsum2, g_bsum2);
    cudaGetSymbolAddress((void**)&wcat_p, g_wcat_p);
    cudaGetSymbolAddress((void**)&wcat_a, g_wcat_a);
    cudaGetSymbolAddress((void**)&wcat_f, g_wcat_f);
    cudaGetSymbolAddress((void**)&cnt, g_cnt);
    cudaGetSymbolAddress((void**)&rowptr, g_rowptr);
    cudaGetSymbolAddress((void**)&cursor, g_cursor);
    cudaGetSymbolAddress((void**)&partials, g_partials);
    cudaGetSymbolAddress((void**)&csr, g_csr);

    const int TPB = 256;
    const int SCAN_NBLK = (NTOT + 1023) / 1024;   // 440

    // ---- summed self-weights / biases ----
    wsum3_kernel<<<(F_IN * HID + TPB - 1) / TPB, TPB>>>(wr1_wr, wr1_ci, wr1_rh, wsum1p, F_IN * HID);
    wsum3_kernel<<<1, TPB>>>(b1_wr, b1_ci, b1_rh, bsum1p, HID);
    wsum3_kernel<<<(HID * OUTF + TPB - 1) / TPB, TPB>>>(wr2_wr, wr2_ci, wr2_rh, wsum2, HID * OUTF);
    wsum3_kernel<<<(OUTF + TPB - 1) / TPB, TPB>>>(b2_wr, b2_ci, b2_rh, bsum2, OUTF);

    // ---- concat weights for fused projections ----
    concat_w<<<(F_IN * 512 + TPB - 1) / TPB, TPB>>>(
        wl1_rw, wl1_ci, wl1_ht, wsum1p,
        wl1_wr, wr1_rw,
        wl1_rh, wr1_ht,
        wcat_p, wcat_a, wcat_f);

    // ---- fused layer-1 projections (3 launches) ----
    {
        dim3 gp(4, (N_PAPER + 127) / 128);
        gemm_proj_multi<<<gp, TPB>>>(x_paper, wcat_p, 256,
                                     h_rw, h_ci, h_ht, p1,
                                     nullptr, nullptr, nullptr, bsum1p, N_PAPER);
        dim3 ga(2, (N_AUTHOR + 127) / 128);
        gemm_proj_multi<<<ga, TPB>>>(x_author, wcat_a, 128,
                                     h_wr, a1, nullptr, nullptr,
                                     nullptr, b1_rw, nullptr, nullptr, N_AUTHOR);
        dim3 gf(2, (N_FIELD + 127) / 128);
        gemm_proj_multi<<<gf, TPB>>>(x_field, wcat_f, 128,
                                     h_rh, f1, nullptr, nullptr,
                                     nullptr, b1_ht, nullptr, nullptr, N_FIELD);
    }

    // ---- CSR build: zero counts -> histogram -> scan -> reorder ----
    zero_cnt_kernel<<<(NTOT / 4 + TPB - 1) / TPB, TPB>>>((int4*)cnt, NTOT / 4);
    count_kernel<<<(E_WR + TPB - 1) / TPB, TPB>>>(ei_wr + E_WR, cnt + B_WR, E_WR);
    count_kernel<<<(E_CI + TPB - 1) / TPB, TPB>>>(ei_ci + E_CI, cnt + B_CI, E_CI);
    count_kernel<<<(E_RH + TPB - 1) / TPB, TPB>>>(ei_rh + E_RH, cnt + B_RH, E_RH);
    count_kernel<<<(E_RW + TPB - 1) / TPB, TPB>>>(ei_rw + E_RW, cnt + B_RW, E_RW);
    count_kernel<<<(E_HT + TPB - 1) / TPB, TPB>>>(ei_ht + E_HT, cnt + B_HT, E_HT);

    scan1_kernel<<<SCAN_NBLK, 256>>>(cnt, rowptr, partials);
    scan2_kernel<<<1, 512>>>(partials, SCAN_NBLK);
    scan3_kernel<<<(NTOT + TPB - 1) / TPB, TPB>>>(rowptr, partials, cursor);

    reorder_kernel<<<(E_WR + TPB - 1) / TPB, TPB>>>(ei_wr, E_WR, B_WR, cursor, csr);
    reorder_kernel<<<(E_CI + TPB - 1) / TPB, TPB>>>(ei_ci, E_CI, B_CI, cursor, csr);
    reorder_kernel<<<(E_RH + TPB - 1) / TPB, TPB>>>(ei_rh, E_RH, B_RH, cursor, csr);
    reorder_kernel<<<(E_RW + TPB - 1) / TPB, TPB>>>(ei_rw, E_RW, B_RW, cursor, csr);
    reorder_kernel<<<(E_HT + TPB - 1) / TPB, TPB>>>(ei_ht, E_HT, B_HT, cursor, csr);

    // ---- layer-1 aggregation (fused mean + self + relu), warp per dst ----
    agg_paper_fin<<<(N_PAPER * 32 + TPB - 1) / TPB, TPB>>>(
        (const __half2*)h_wr, (const __half2*)h_ci, (const __half2*)h_rh,
        csr, rowptr, (__half2*)p1);
    agg_fin_one<<<(N_AUTHOR * 32 + TPB - 1) / TPB, TPB>>>(
        (const __half2*)h_rw, csr, rowptr, B_RW, N_AUTHOR, (__half2*)a1);
    agg_fin_one<<<(N_FIELD * 32 + TPB - 1) / TPB, TPB>>>(
        (const __half2*)h_ht, csr, rowptr, B_HT, N_FIELD, (__half2*)f1);

    // ---- layer-2 aggregation (all three means, one launch) ----
    agg_mean3<<<(3 * N_PAPER * 32 + TPB - 1) / TPB, TPB>>>(
        (const __half2*)a1, (const __half2*)p1, (const __half2*)f1,
        csr, rowptr,
        (__half2*)acc2_wr, (__half2*)acc2_ci, (__half2*)acc2_rh);

    // ---- fused output GEMM: [100k x 4x64] @ [4x64 x 349] + bias ----
    {
        dim3 grid((OUTF + 63) / 64, (N_PAPER + 127) / 128);
        gemm_out_tc<<<grid, TPB>>>(acc2_wr, acc2_ci, acc2_rh, p1,
                                   wl2_wr, wl2_ci, wl2_rh, wsum2,
                                   bsum2, out, N_PAPER);
    }
}

// round 15
// speedup vs baseline: 3.2960x; 1.2780x over previous
#include <cuda_runtime.h>
#include <cuda_fp16.h>
#include <cstdint>

// ---------------- problem constants ----------------
#define N_PAPER  100000
#define N_AUTHOR 100000
#define N_FIELD  50000
#define F_IN 128
#define HID  64
#define OUTF 349
#define E_WR 1000000
#define E_RW 1000000
#define E_CI 2000000
#define E_HT 1000000
#define E_RH 1000000
#define E_TOT 6000000

// global (node,type) slot bases for the concatenated CSR
#define B_WR 0          // dst = paper
#define B_CI 100000     // dst = paper
#define B_RH 200000     // dst = paper
#define B_RW 300000     // dst = author
#define B_HT 400000     // dst = field
#define NTOT 450000

// ---------------- scratch (static device memory; no allocs) ----------------
__device__ __half g_h_wr[N_AUTHOR * HID];
__device__ __half g_h_rw[N_PAPER  * HID];
__device__ __half g_h_ci[N_PAPER  * HID];
__device__ __half g_h_ht[N_PAPER  * HID];
__device__ __half g_h_rh[N_FIELD  * HID];

__device__ __half g_p1[N_PAPER  * HID];
__device__ __half g_a1[N_AUTHOR * HID];
__device__ __half g_f1[N_FIELD  * HID];

__device__ __half g_acc2_wr[N_PAPER * HID];
__device__ __half g_acc2_ci[N_PAPER * HID];
__device__ __half g_acc2_rh[N_PAPER * HID];

__device__ float g_wsum1p[F_IN * HID];
__device__ float g_bsum1p[HID];
__device__ float g_wsum2[HID * OUTF];
__device__ float g_bsum2[OUTF];

__device__ float g_wcat_p[F_IN * 256];   // [wl1_rw | wl1_ci | wl1_ht | wsum1p]
__device__ float g_wcat_a[F_IN * 128];   // [wl1_wr | wr1_rw]
__device__ float g_wcat_f[F_IN * 128];   // [wl1_rh | wr1_ht]

__device__ int g_cnt[NTOT];
__device__ int g_rowptr[NTOT + 1];
__device__ int g_cursor[NTOT];
__device__ int g_partials[512];
__device__ int g_csr[E_TOT];

// ---------------- small helper kernels ----------------

__global__ void zero_cnt_kernel(int4* __restrict__ p, int n4) {
    int idx = blockIdx.x * blockDim.x + threadIdx.x;
    if (idx < n4) p[idx] = make_int4(0, 0, 0, 0);
}

__global__ void wsum3_kernel(const float* __restrict__ w0, const float* __restrict__ w1,
                             const float* __restrict__ w2, float* __restrict__ out, int n) {
    int idx = blockIdx.x * blockDim.x + threadIdx.x;
    if (idx < n) out[idx] = w0[idx] + w1[idx] + w2[idx];
}

// concatenate 8 [128x64] weight blocks into the 3 wcat buffers
__global__ void concat_w(const float* __restrict__ s0, const float* __restrict__ s1,
                         const float* __restrict__ s2, const float* __restrict__ s3,
                         const float* __restrict__ s4, const float* __restrict__ s5,
                         const float* __restrict__ s6, const float* __restrict__ s7,
                         float* __restrict__ wp, float* __restrict__ wa,
                         float* __restrict__ wf) {
    int idx = blockIdx.x * blockDim.x + threadIdx.x;   // 128*512 = 65536 total
    if (idx >= F_IN * 512) return;
    int seg = idx >> 13;
    int e = idx & 8191;
    int k = e >> 6, c = e & 63;
    const float* srcs[8] = {s0, s1, s2, s3, s4, s5, s6, s7};
    float v = srcs[seg][k * 64 + c];
    if (seg < 4)      wp[k * 256 + seg * 64 + c] = v;
    else if (seg < 6) wa[k * 128 + (seg - 4) * 64 + c] = v;
    else              wf[k * 128 + (seg - 6) * 64 + c] = v;
}

// fused histogram over all 5 edge types (order: wr, ci, rh, rw, ht)
__global__ void count_all(const int* __restrict__ e_wr, const int* __restrict__ e_ci,
                          const int* __restrict__ e_rh, const int* __restrict__ e_rw,
                          const int* __restrict__ e_ht, int* __restrict__ cnt) {
    int i = blockIdx.x * blockDim.x + threadIdx.x;
    if (i >= E_TOT) return;
    const int* dst; int base;
    if (i < E_WR)                    { dst = e_wr + E_WR; base = B_WR; }
    else if ((i -= E_WR) < E_CI)     { dst = e_ci + E_CI; base = B_CI; }
    else if ((i -= E_CI) < E_RH)     { dst = e_rh + E_RH; base = B_RH; }
    else if ((i -= E_RH) < E_RW)     { dst = e_rw + E_RW; base = B_RW; }
    else       { i -= E_RW;            dst = e_ht + E_HT; base = B_HT; }
    atomicAdd(&cnt[base + __ldg(&dst[i])], 1);
}

// fused reorder over all 5 edge types
__global__ void reorder_all(const int* __restrict__ e_wr, const int* __restrict__ e_ci,
                            const int* __restrict__ e_rh, const int* __restrict__ e_rw,
                            const int* __restrict__ e_ht,
                            int* __restrict__ cursor, int* __restrict__ csr) {
    int i = blockIdx.x * blockDim.x + threadIdx.x;
    if (i >= E_TOT) return;
    const int* ei; int base, E;
    if (i < E_WR)                    { ei = e_wr; base = B_WR; E = E_WR; }
    else if ((i -= E_WR) < E_CI)     { ei = e_ci; base = B_CI; E = E_CI; }
    else if ((i -= E_CI) < E_RH)     { ei = e_rh; base = B_RH; E = E_RH; }
    else if ((i -= E_RH) < E_RW)     { ei = e_rw; base = B_RW; E = E_RW; }
    else       { i -= E_RW;            ei = e_ht; base = B_HT; E = E_HT; }
    int s = __ldg(&ei[i]);
    int d = __ldg(&ei[E + i]);
    int pos = atomicAdd(&cursor[base + d], 1);
    csr[pos] = s;
}

// ---- fused exclusive scan over 450k counts (3 kernels) ----
__global__ void scan1_kernel(const int* __restrict__ cnt, int* __restrict__ rp,
                             int* __restrict__ partials) {
    __shared__ int s[256];
    int t = threadIdx.x, b = blockIdx.x;
    int i0 = b * 1024 + t * 4;
    int c0 = (i0     < NTOT) ? cnt[i0]     : 0;
    int c1 = (i0 + 1 < NTOT) ? cnt[i0 + 1] : 0;
    int c2 = (i0 + 2 < NTOT) ? cnt[i0 + 2] : 0;
    int c3 = (i0 + 3 < NTOT) ? cnt[i0 + 3] : 0;
    int ts = c0 + c1 + c2 + c3;
    s[t] = ts;
    __syncthreads();
    for (int off = 1; off < 256; off <<= 1) {
        int v = (t >= off) ? s[t - off] : 0;
        __syncthreads();
        s[t] += v;
        __syncthreads();
    }
    int p = s[t] - ts;
    if (t == 255) partials[b] = s[255];
    if (i0     < NTOT) rp[i0]     = p; p += c0;
    if (i0 + 1 < NTOT) rp[i0 + 1] = p; p += c1;
    if (i0 + 2 < NTOT) rp[i0 + 2] = p; p += c2;
    if (i0 + 3 < NTOT) rp[i0 + 3] = p;
}

__global__ void scan2_kernel(int* __restrict__ partials, int nblk) {
    __shared__ int s[512];
    int t = threadIdx.x;
    int v0 = (t < nblk) ? partials[t] : 0;
    s[t] = v0;
    __syncthreads();
    for (int off = 1; off < 512; off <<= 1) {
        int v = (t >= off) ? s[t - off] : 0;
        __syncthreads();
        s[t] += v;
        __syncthreads();
    }
    if (t < nblk) partials[t] = s[t] - v0;
}

__global__ void scan3_kernel(int* __restrict__ rp, const int* __restrict__ partials,
                             int* __restrict__ cursor) {
    int i = blockIdx.x * blockDim.x + threadIdx.x;
    if (i < NTOT) {
        int v = rp[i] + partials[i >> 10];
        rp[i] = v;
        cursor[i] = v;
    }
    if (i == 0) rp[NTOT] = E_TOT;
}

// ---- CSR-based aggregation: warp per destination, half2 per lane, fp32 accum ----

__device__ __forceinline__ float2 h2f(__half2 h) { return __half22float2(h); }
__device__ __forceinline__ __half2 f2h(float x, float y) {
    return __floats2half2_rn(x, y);
}

__global__ void agg_paper_fin(const __half2* __restrict__ hwr, const __half2* __restrict__ hci,
                              const __half2* __restrict__ hrh,
                              const int* __restrict__ csr, const int* __restrict__ rp,
                              __half2* __restrict__ p) {
    int gw = (blockIdx.x * blockDim.x + threadIdx.x) >> 5;
    int lane = threadIdx.x & 31;
    if (gw >= N_PAPER) return;
    float2 tot = h2f(p[gw * 32 + lane]);
    const __half2* feats[3] = {hwr, hci, hrh};
    #pragma unroll
    for (int t = 0; t < 3; t++) {
        int s = __ldg(&rp[t * 100000 + gw]);
        int e = __ldg(&rp[t * 100000 + gw + 1]);
        float2 acc = make_float2(0.f, 0.f);
        const __half2* f = feats[t];
        #pragma unroll 4
        for (int i = s; i < e; i++) {
            int sv = __ldg(&csr[i]);
            float2 v = h2f(__ldg(&f[sv * 32 + lane]));
            acc.x += v.x; acc.y += v.y;
        }
        float r = (e > s) ? 1.0f / (float)(e - s) : 0.f;
        tot.x += acc.x * r; tot.y += acc.y * r;
    }
    p[gw * 32 + lane] = f2h(fmaxf(tot.x, 0.f), fmaxf(tot.y, 0.f));
}

__global__ void agg_fin_one(const __half2* __restrict__ feat, const int* __restrict__ csr,
                            const int* __restrict__ rp, int base, int n,
                            __half2* __restrict__ y) {
    int gw = (blockIdx.x * blockDim.x + threadIdx.x) >> 5;
    int lane = threadIdx.x & 31;
    if (gw >= n) return;
    int s = __ldg(&rp[base + gw]);
    int e = __ldg(&rp[base + gw + 1]);
    float2 acc = make_float2(0.f, 0.f);
    #pragma unroll 4
    for (int i = s; i < e; i++) {
        int sv = __ldg(&csr[i]);
        float2 v = h2f(__ldg(&feat[sv * 32 + lane]));
        acc.x += v.x; acc.y += v.y;
    }
    float r = (e > s) ? 1.0f / (float)(e - s) : 0.f;
    float2 t = h2f(y[gw * 32 + lane]);
    y[gw * 32 + lane] = f2h(fmaxf(t.x + acc.x * r, 0.f), fmaxf(t.y + acc.y * r, 0.f));
}

__global__ void agg_mean3(const __half2* __restrict__ fa, const __half2* __restrict__ fp,
                          const __half2* __restrict__ ff,
                          const int* __restrict__ csr, const int* __restrict__ rp,
                          __half2* __restrict__ oa, __half2* __restrict__ op,
                          __half2* __restrict__ of) {
    int gw = (blockIdx.x * blockDim.x + threadIdx.x) >> 5;
    int lane = threadIdx.x & 31;
    if (gw >= 3 * N_PAPER) return;
    int t = gw / N_PAPER;
    int node = gw - t * N_PAPER;
    const __half2* f = (t == 0) ? fa : (t == 1) ? fp : ff;
    __half2* o       = (t == 0) ? oa : (t == 1) ? op : of;
    int base = t * 100000;
    int s = __ldg(&rp[base + node]);
    int e = __ldg(&rp[base + node + 1]);
    float2 acc = make_float2(0.f, 0.f);
    #pragma unroll 4
    for (int i = s; i < e; i++) {
        int sv = __ldg(&csr[i]);
        float2 v = h2f(__ldg(&f[sv * 32 + lane]));
        acc.x += v.x; acc.y += v.y;
    }
    float r = (e > s) ? 1.0f / (float)(e - s) : 0.f;
    o[node * 32 + lane] = f2h(acc.x * r, acc.y * r);
}

// ---------------- fp16 tensor-core GEMMs (m16n8k16, fp32 accum) ----------------

__device__ __forceinline__ void mma16(float* c, const unsigned* a, const unsigned* b) {
    asm volatile("mma.sync.aligned.m16n8k16.row.col.f32.f16.f16.f32 "
        "{%0,%1,%2,%3}, {%4,%5,%6,%7}, {%8,%9}, {%0,%1,%2,%3};"
        : "+f"(c[0]), "+f"(c[1]), "+f"(c[2]), "+f"(c[3])
        : "r"(a[0]), "r"(a[1]), "r"(a[2]), "r"(a[3]), "r"(b[0]), "r"(b[1]));
}

// smem strides (4B words). 36 is conflict-free for (gid 0..7, tig 0..3):
// (36*g + t) mod 32 all distinct.
#define AST 36   // A: 128 rows x 32 half2 (K-chunk 64) + pad
#define WST 36   // W: 64 n-rows x 32 half2 + pad

// Multi-output projection GEMM: C_j[M x 64] = A[M x 128] @ Wcat[:, j*64:(j+1)*64] (+ bias_j)
// fp32 in global, fp16 mma (fp32 accum), fp16 out. K-chunk 64 (2 chunks).
__global__ __launch_bounds__(256) void gemm_proj_multi(
    const float* __restrict__ A, const float* __restrict__ W, int ldw,
    __half* o0, __half* o1, __half* o2, __half* o3,
    const float* b0, const float* b1, const float* b2, const float* b3, int M)
{
    __shared__ unsigned As[128][AST];   // half2 packed along k
    __shared__ unsigned Ws[64][WST];    // [n][kpair] half2
    const int tid = threadIdx.x;
    const int warp = tid >> 5, lane = tid & 31;
    const int gid = lane >> 2, tig = lane & 3;
    const int wm = (warp & 3) * 32;
    const int wn = (warp >> 2) * 32;
    const int row0 = blockIdx.y * 128;
    const int wc0 = blockIdx.x * 64;

    __half* C;
    const float* bias;
    switch (blockIdx.x) {
        case 0: C = o0; bias = b0; break;
        case 1: C = o1; bias = b1; break;
        case 2: C = o2; bias = b2; break;
        default: C = o3; bias = b3; break;
    }

    float acc[2][4][4] = {};

    #pragma unroll 1
    for (int kk = 0; kk < F_IN; kk += 64) {
        // A chunk: 128 rows x 64 k; one float4 -> 2 half2 words
        for (int i = tid; i < 128 * 16; i += 256) {
            int r = i >> 4, q = i & 15;
            int rg = row0 + r;
            float4 v = make_float4(0.f, 0.f, 0.f, 0.f);
            if (rg < M) v = *(const float4*)&A[rg * F_IN + kk + q * 4];
            __half2 h0 = __floats2half2_rn(v.x, v.y);
            __half2 h1 = __floats2half2_rn(v.z, v.w);
            As[r][q * 2]     = *(unsigned*)&h0;
            As[r][q * 2 + 1] = *(unsigned*)&h1;
        }
        // W chunk: Ws[n][kp] = half2(W[kk+2kp][wc0+n], W[kk+2kp+1][wc0+n])
        for (int i = tid; i < 64 * 32; i += 256) {
            int n = i & 63, kp = i >> 6;
            float w0 = W[(kk + 2 * kp) * ldw + wc0 + n];
            float w1 = W[(kk + 2 * kp + 1) * ldw + wc0 + n];
            __half2 h = __floats2half2_rn(w0, w1);
            Ws[n][kp] = *(unsigned*)&h;
        }
        __syncthreads();
        #pragma unroll
        for (int kt = 0; kt < 4; kt++) {
            int k0h = kt * 8;   // 16 k-values = 8 half2
            unsigned a[2][4], b[4][2];
            #pragma unroll
            for (int mi = 0; mi < 2; mi++) {
                int r = wm + mi * 16 + gid;
                a[mi][0] = As[r][k0h + tig];
                a[mi][1] = As[r + 8][k0h + tig];
                a[mi][2] = As[r][k0h + tig + 4];
                a[mi][3] = As[r + 8][k0h + tig + 4];
            }
            #pragma unroll
            for (int ni = 0; ni < 4; ni++) {
                int n = wn + ni * 8 + gid;
                b[ni][0] = Ws[n][k0h + tig];
                b[ni][1] = Ws[n][k0h + tig + 4];
            }
            #pragma unroll
            for (int mi = 0; mi < 2; mi++)
                #pragma unroll
                for (int ni = 0; ni < 4; ni++)
                    mma16(acc[mi][ni], a[mi], b[ni]);
        }
        __syncthreads();
    }

    #pragma unroll
    for (int ni = 0; ni < 4; ni++) {
        int col = wn + ni * 8 + tig * 2;
        float2 bv = make_float2(0.f, 0.f);
        if (bias) bv = *(const float2*)&bias[col];
        #pragma unroll
        for (int mi = 0; mi < 2; mi++) {
            int r = row0 + wm + mi * 16 + gid;
            if (r < M)
                *(__half2*)&C[r * HID + col] =
                    __floats2half2_rn(acc[mi][ni][0] + bv.x, acc[mi][ni][1] + bv.y);
            if (r + 8 < M)
                *(__half2*)&C[(r + 8) * HID + col] =
                    __floats2half2_rn(acc[mi][ni][2] + bv.x, acc[mi][ni][3] + bv.y);
        }
    }
}

// C[M x 349] = sum_t A_t[M x 64] @ W_t[64 x 349] + bias  (A_t fp16 global, W fp32)
// K per t = 64 = one chunk; 4 t-sweeps.
__global__ __launch_bounds__(256) void gemm_out_tc(
    const __half* __restrict__ A0, const __half* __restrict__ A1,
    const __half* __restrict__ A2, const __half* __restrict__ A3,
    const float* __restrict__ W0, const float* __restrict__ W1,
    const float* __restrict__ W2, const float* __restrict__ W3,
    const float* __restrict__ bias, float* __restrict__ C, int M)
{
    __shared__ unsigned As[128][AST];
    __shared__ unsigned Ws[64][WST];
    const int tid = threadIdx.x;
    const int warp = tid >> 5, lane = tid & 31;
    const int gid = lane >> 2, tig = lane & 3;
    const int wm = (warp & 3) * 32;
    const int wn = (warp >> 2) * 32;
    const int row0 = blockIdx.y * 128;
    const int col0 = blockIdx.x * 64;

    const __half* Aps[4] = {A0, A1, A2, A3};
    const float* Wps[4] = {W0, W1, W2, W3};

    float acc[2][4][4] = {};

    #pragma unroll 1
    for (int t = 0; t < 4; t++) {
        const __half* A = Aps[t];
        const float* W = Wps[t];
        // A: 128 rows x 64 halves = 8 uint4 per row (fp16 direct copy)
        for (int i = tid; i < 128 * 8; i += 256) {
            int r = i >> 3, q = i & 7;
            int rg = row0 + r;
            uint4 v = make_uint4(0u, 0u, 0u, 0u);
            if (rg < M) v = *(const uint4*)&A[rg * HID + q * 8];
            *(uint4*)&As[r][q * 4] = v;
        }
        // W: Ws[n][kp] = half2(W[2kp][col0+n], W[2kp+1][col0+n]) with OUTF bounds
        for (int i = tid; i < 64 * 32; i += 256) {
            int n = i & 63, kp = i >> 6;
            int cg = col0 + n;
            float w0 = 0.f, w1 = 0.f;
            if (cg < OUTF) {
                w0 = W[(2 * kp) * OUTF + cg];
                w1 = W[(2 * kp + 1) * OUTF + cg];
            }
            __half2 h = __floats2half2_rn(w0, w1);
            Ws[n][kp] = *(unsigned*)&h;
        }
        __syncthreads();
        #pragma unroll
        for (int kt = 0; kt < 4; kt++) {
            int k0h = kt * 8;
            unsigned a[2][4], b[4][2];
            #pragma unroll
            for (int mi = 0; mi < 2; mi++) {
                int r = wm + mi * 16 + gid;
                a[mi][0] = As[r][k0h + tig];
                a[mi][1] = As[r + 8][k0h + tig];
                a[mi][2] = As[r][k0h + tig + 4];
                a[mi][3] = As[r + 8][k0h + tig + 4];
            }
            #pragma unroll
            for (int ni = 0; ni < 4; ni++) {
                int n = wn + ni * 8 + gid;
                b[ni][0] = Ws[n][k0h + tig];
                b[ni][1] = Ws[n][k0h + tig + 4];
            }
            #pragma unroll
            for (int mi = 0; mi < 2; mi++)
                #pragma unroll
                for (int ni = 0; ni < 4; ni++)
                    mma16(acc[mi][ni], a[mi], b[ni]);
        }
        __syncthreads();
    }

    #pragma unroll
    for (int ni = 0; ni < 4; ni++) {
        int col = col0 + wn + ni * 8 + tig * 2;
        float b0v = (col < OUTF) ? bias[col] : 0.f;
        float b1v = (col + 1 < OUTF) ? bias[col + 1] : 0.f;
        #pragma unroll
        for (int mi = 0; mi < 2; mi++) {
            int r = row0 + wm + mi * 16 + gid;
            if (r < M) {
                if (col < OUTF)     C[r * OUTF + col]     = acc[mi][ni][0] + b0v;
                if (col + 1 < OUTF) C[r * OUTF + col + 1] = acc[mi][ni][1] + b1v;
            }
            int r2 = r + 8;
            if (r2 < M) {
                if (col < OUTF)     C[r2 * OUTF + col]     = acc[mi][ni][2] + b0v;
                if (col + 1 < OUTF) C[r2 * OUTF + col + 1] = acc[mi][ni][3] + b1v;
            }
        }
    }
}

// ---------------- host launcher ----------------
extern "C" void kernel_launch(void* const* d_in, const int* in_sizes, int n_in,
                              void* d_out, int out_size) {
    (void)in_sizes; (void)n_in; (void)out_size;
    const float* x_paper  = (const float*)d_in[0];
    const float* x_author = (const float*)d_in[1];
    const float* x_field  = (const float*)d_in[2];
    const int* ei_wr = (const int*)d_in[3];
    const int* ei_rw = (const int*)d_in[4];
    const int* ei_ci = (const int*)d_in[5];
    const int* ei_ht = (const int*)d_in[6];
    const int* ei_rh = (const int*)d_in[7];
    const float* wl1_wr = (const float*)d_in[8];
    const float* wr1_wr = (const float*)d_in[9];
    const float* b1_wr  = (const float*)d_in[10];
    const float* wl1_rw = (const float*)d_in[11];
    const float* wr1_rw = (const float*)d_in[12];
    const float* b1_rw  = (const float*)d_in[13];
    const float* wl1_ci = (const float*)d_in[14];
    const float* wr1_ci = (const float*)d_in[15];
    const float* b1_ci  = (const float*)d_in[16];
    const float* wl1_ht = (const float*)d_in[17];
    const float* wr1_ht = (const float*)d_in[18];
    const float* b1_ht  = (const float*)d_in[19];
    const float* wl1_rh = (const float*)d_in[20];
    const float* wr1_rh = (const float*)d_in[21];
    const float* b1_rh  = (const float*)d_in[22];
    const float* wl2_wr = (const float*)d_in[23];
    const float* wr2_wr = (const float*)d_in[24];
    const float* b2_wr  = (const float*)d_in[25];
    const float* wl2_ci = (const float*)d_in[26];
    const float* wr2_ci = (const float*)d_in[27];
    const float* b2_ci  = (const float*)d_in[28];
    const float* wl2_rh = (const float*)d_in[29];
    const float* wr2_rh = (const float*)d_in[30];
    const float* b2_rh  = (const float*)d_in[31];
    float* out = (float*)d_out;

    __half *h_wr, *h_rw, *h_ci, *h_ht, *h_rh, *p1, *a1, *f1;
    __half *acc2_wr, *acc2_ci, *acc2_rh;
    float *wsum1p, *bsum1p, *wsum2, *bsum2;
    float *wcat_p, *wcat_a, *wcat_f;
    int *cnt, *rowptr, *cursor, *partials, *csr;
    cudaGetSymbolAddress((void**)&h_wr, g_h_wr);
    cudaGetSymbolAddress((void**)&h_rw, g_h_rw);
    cudaGetSymbolAddress((void**)&h_ci, g_h_ci);
    cudaGetSymbolAddress((void**)&h_ht, g_h_ht);
    cudaGetSymbolAddress((void**)&h_rh, g_h_rh);
    cudaGetSymbolAddress((void**)&p1, g_p1);
    cudaGetSymbolAddress((void**)&a1, g_a1);
    cudaGetSymbolAddress((void**)&f1, g_f1);
    cudaGetSymbolAddress((void**)&acc2_wr, g_acc2_wr);
    cudaGetSymbolAddress((void**)&acc2_ci, g_acc2_ci);
    cudaGetSymbolAddress((void**)&acc2_rh, g_acc2_rh);
    cudaGetSymbolAddress((void**)&wsum1p, g_wsum1p);
    cudaGetSymbolAddress((void**)&bsum1p, g_bsum1p);
    cudaGetSymbolAddress((void**)&wsum2, g_wsum2);
    cudaGetSymbolAddress((void**)&bsum2, g_bsum2);
    cudaGetSymbolAddress((void**)&wcat_p, g_wcat_p);
    cudaGetSymbolAddress((void**)&wcat_a, g_wcat_a);
    cudaGetSymbolAddress((void**)&wcat_f, g_wcat_f);
    cudaGetSymbolAddress((void**)&cnt, g_cnt);
    cudaGetSymbolAddress((void**)&rowptr, g_rowptr);
    cudaGetSymbolAddress((void**)&cursor, g_cursor);
    cudaGetSymbolAddress((void**)&partials, g_partials);
    cudaGetSymbolAddress((void**)&csr, g_csr);

    const int TPB = 256;
    const int SCAN_NBLK = (NTOT + 1023) / 1024;   // 440

    // ---- summed self-weights / biases ----
    wsum3_kernel<<<(F_IN * HID + TPB - 1) / TPB, TPB>>>(wr1_wr, wr1_ci, wr1_rh, wsum1p, F_IN * HID);
    wsum3_kernel<<<1, TPB>>>(b1_wr, b1_ci, b1_rh, bsum1p, HID);
    wsum3_kernel<<<(HID * OUTF + TPB - 1) / TPB, TPB>>>(wr2_wr, wr2_ci, wr2_rh, wsum2, HID * OUTF);
    wsum3_kernel<<<(OUTF + TPB - 1) / TPB, TPB>>>(b2_wr, b2_ci, b2_rh, bsum2, OUTF);

    // ---- concat weights for fused projections ----
    concat_w<<<(F_IN * 512 + TPB - 1) / TPB, TPB>>>(
        wl1_rw, wl1_ci, wl1_ht, wsum1p,
        wl1_wr, wr1_rw,
        wl1_rh, wr1_ht,
        wcat_p, wcat_a, wcat_f);

    // ---- fused layer-1 projections (3 launches) ----
    {
        dim3 gp(4, (N_PAPER + 127) / 128);
        gemm_proj_multi<<<gp, TPB>>>(x_paper, wcat_p, 256,
                                     h_rw, h_ci, h_ht, p1,
                                     nullptr, nullptr, nullptr, bsum1p, N_PAPER);
        dim3 ga(2, (N_AUTHOR + 127) / 128);
        gemm_proj_multi<<<ga, TPB>>>(x_author, wcat_a, 128,
                                     h_wr, a1, nullptr, nullptr,
                                     nullptr, b1_rw, nullptr, nullptr, N_AUTHOR);
        dim3 gf(2, (N_FIELD + 127) / 128);
        gemm_proj_multi<<<gf, TPB>>>(x_field, wcat_f, 128,
                                     h_rh, f1, nullptr, nullptr,
                                     nullptr, b1_ht, nullptr, nullptr, N_FIELD);
    }

    // ---- CSR build: zero counts -> fused histogram -> scan -> fused reorder ----
    zero_cnt_kernel<<<(NTOT / 4 + TPB - 1) / TPB, TPB>>>((int4*)cnt, NTOT / 4);
    count_all<<<(E_TOT + TPB - 1) / TPB, TPB>>>(ei_wr, ei_ci, ei_rh, ei_rw, ei_ht, cnt);

    scan1_kernel<<<SCAN_NBLK, 256>>>(cnt, rowptr, partials);
    scan2_kernel<<<1, 512>>>(partials, SCAN_NBLK);
    scan3_kernel<<<(NTOT + TPB - 1) / TPB, TPB>>>(rowptr, partials, cursor);

    reorder_all<<<(E_TOT + TPB - 1) / TPB, TPB>>>(ei_wr, ei_ci, ei_rh, ei_rw, ei_ht,
                                                  cursor, csr);

    // ---- layer-1 aggregation (fused mean + self + relu), warp per dst ----
    agg_paper_fin<<<(N_PAPER * 32 + TPB - 1) / TPB, TPB>>>(
        (const __half2*)h_wr, (const __half2*)h_ci, (const __half2*)h_rh,
        csr, rowptr, (__half2*)p1);
    agg_fin_one<<<(N_AUTHOR * 32 + TPB - 1) / TPB, TPB>>>(
        (const __half2*)h_rw, csr, rowptr, B_RW, N_AUTHOR, (__half2*)a1);
    agg_fin_one<<<(N_FIELD * 32 + TPB - 1) / TPB, TPB>>>(
        (const __half2*)h_ht, csr, rowptr, B_HT, N_FIELD, (__half2*)f1);

    // ---- layer-2 aggregation (all three means, one launch) ----
    agg_mean3<<<(3 * N_PAPER * 32 + TPB - 1) / TPB, TPB>>>(
        (const __half2*)a1, (const __half2*)p1, (const __half2*)f1,
        csr, rowptr,
        (__half2*)acc2_wr, (__half2*)acc2_ci, (__half2*)acc2_rh);

    // ---- fused output GEMM: [100k x 4x64] @ [4x64 x 349] + bias ----
    {
        dim3 grid((OUTF + 63) / 64, (N_PAPER + 127) / 128);
        gemm_out_tc<<<grid, TPB>>>(acc2_wr, acc2_ci, acc2_rh, p1,
                                   wl2_wr, wl2_ci, wl2_rh, wsum2,
                                   bsum2, out, N_PAPER);
    }
}

// round 16
// speedup vs baseline: 3.3877x; 1.0278x over previous
#include <cuda_runtime.h>
#include <cuda_fp16.h>
#include <cstdint>

// ---------------- problem constants ----------------
#define N_PAPER  100000
#define N_AUTHOR 100000
#define N_FIELD  50000
#define F_IN 128
#define HID  64
#define OUTF 349
#define E_WR 1000000
#define E_RW 1000000
#define E_CI 2000000
#define E_HT 1000000
#define E_RH 1000000
#define E_TOT 6000000

// global (node,type) slot bases for the concatenated CSR
#define B_WR 0          // dst = paper
#define B_CI 100000     // dst = paper
#define B_RH 200000     // dst = paper
#define B_RW 300000     // dst = author
#define B_HT 400000     // dst = field
#define NTOT 450000

// ---------------- scratch (static device memory; no allocs) ----------------
__device__ __half g_h_wr[N_AUTHOR * HID];
__device__ __half g_h_rw[N_PAPER  * HID];
__device__ __half g_h_ci[N_PAPER  * HID];
__device__ __half g_h_ht[N_PAPER  * HID];
__device__ __half g_h_rh[N_FIELD  * HID];

__device__ __half g_p1[N_PAPER  * HID];
__device__ __half g_a1[N_AUTHOR * HID];
__device__ __half g_f1[N_FIELD  * HID];

__device__ __half g_acc2_wr[N_PAPER * HID];
__device__ __half g_acc2_ci[N_PAPER * HID];
__device__ __half g_acc2_rh[N_PAPER * HID];

__device__ float g_bsum1p[HID];
__device__ float g_wsum2[HID * OUTF];
__device__ float g_bsum2[OUTF];

__device__ float g_wcat_p[F_IN * 256];   // [wl1_rw | wl1_ci | wl1_ht | wsum1p]
__device__ float g_wcat_a[F_IN * 128];   // [wl1_wr | wr1_rw]
__device__ float g_wcat_f[F_IN * 128];   // [wl1_rh | wr1_ht]

__device__ int g_cnt[NTOT];
__device__ int g_rowptr[NTOT + 1];
__device__ int g_cursor[NTOT];
__device__ int g_partials[512];
__device__ int g_csr[E_TOT];

// ---------------- fused prep kernel: all weight sums + concat ----------------
// regions (by idx):
//   [0, 22336)            wsum2   = wr2_wr + wr2_ci + wr2_rh
//   [22336, 22685)        bsum2   = b2_wr + b2_ci + b2_rh
//   [22685, 22749)        bsum1p  = b1_wr + b1_ci + b1_rh
//   [22749, 55517)        wcat_p  (4 tiles of 128x64; tile3 = wr1_wr+wr1_ci+wr1_rh)
//   [55517, 71901)        wcat_a  (2 tiles)
//   [71901, 88285)        wcat_f  (2 tiles)
#define PREP_TOT 88285
__global__ void prep_kernel(
    const float* __restrict__ wr2_wr, const float* __restrict__ wr2_ci,
    const float* __restrict__ wr2_rh,
    const float* __restrict__ b2_wr, const float* __restrict__ b2_ci,
    const float* __restrict__ b2_rh,
    const float* __restrict__ b1_wr, const float* __restrict__ b1_ci,
    const float* __restrict__ b1_rh,
    const float* __restrict__ wl1_rw, const float* __restrict__ wl1_ci,
    const float* __restrict__ wl1_ht,
    const float* __restrict__ wr1_wr, const float* __restrict__ wr1_ci,
    const float* __restrict__ wr1_rh,
    const float* __restrict__ wl1_wr, const float* __restrict__ wr1_rw,
    const float* __restrict__ wl1_rh, const float* __restrict__ wr1_ht,
    float* __restrict__ wsum2, float* __restrict__ bsum2,
    float* __restrict__ bsum1p, float* __restrict__ wcat_p,
    float* __restrict__ wcat_a, float* __restrict__ wcat_f)
{
    int idx = blockIdx.x * blockDim.x + threadIdx.x;
    if (idx >= PREP_TOT) return;
    if (idx < 22336) {
        wsum2[idx] = wr2_wr[idx] + wr2_ci[idx] + wr2_rh[idx];
    } else if (idx < 22685) {
        int i = idx - 22336;
        bsum2[i] = b2_wr[i] + b2_ci[i] + b2_rh[i];
    } else if (idx < 22749) {
        int i = idx - 22685;
        bsum1p[i] = b1_wr[i] + b1_ci[i] + b1_rh[i];
    } else if (idx < 55517) {
        int i = idx - 22749;                 // 0..32767
        int seg = i >> 13, e = i & 8191;
        int k = e >> 6, c = e & 63;
        float v;
        if (seg == 0)      v = wl1_rw[k * 64 + c];
        else if (seg == 1) v = wl1_ci[k * 64 + c];
        else if (seg == 2) v = wl1_ht[k * 64 + c];
        else               v = wr1_wr[k * 64 + c] + wr1_ci[k * 64 + c] + wr1_rh[k * 64 + c];
        wcat_p[k * 256 + seg * 64 + c] = v;
    } else if (idx < 71901) {
        int i = idx - 55517;
        int seg = i >> 13, e = i & 8191;
        int k = e >> 6, c = e & 63;
        float v = (seg == 0) ? wl1_wr[k * 64 + c] : wr1_rw[k * 64 + c];
        wcat_a[k * 128 + seg * 64 + c] = v;
    } else {
        int i = idx - 71901;
        int seg = i >> 13, e = i & 8191;
        int k = e >> 6, c = e & 63;
        float v = (seg == 0) ? wl1_rh[k * 64 + c] : wr1_ht[k * 64 + c];
        wcat_f[k * 128 + seg * 64 + c] = v;
    }
}

// ---------------- CSR build kernels ----------------

__global__ void zero_cnt_kernel(int4* __restrict__ p, int n4) {
    int idx = blockIdx.x * blockDim.x + threadIdx.x;
    if (idx < n4) p[idx] = make_int4(0, 0, 0, 0);
}

__global__ void count_all(const int* __restrict__ e_wr, const int* __restrict__ e_ci,
                          const int* __restrict__ e_rh, const int* __restrict__ e_rw,
                          const int* __restrict__ e_ht, int* __restrict__ cnt) {
    int i = blockIdx.x * blockDim.x + threadIdx.x;
    if (i >= E_TOT) return;
    const int* dst; int base;
    if (i < E_WR)                    { dst = e_wr + E_WR; base = B_WR; }
    else if ((i -= E_WR) < E_CI)     { dst = e_ci + E_CI; base = B_CI; }
    else if ((i -= E_CI) < E_RH)     { dst = e_rh + E_RH; base = B_RH; }
    else if ((i -= E_RH) < E_RW)     { dst = e_rw + E_RW; base = B_RW; }
    else       { i -= E_RW;            dst = e_ht + E_HT; base = B_HT; }
    atomicAdd(&cnt[base + __ldg(&dst[i])], 1);
}

__global__ void reorder_all(const int* __restrict__ e_wr, const int* __restrict__ e_ci,
                            const int* __restrict__ e_rh, const int* __restrict__ e_rw,
                            const int* __restrict__ e_ht,
                            int* __restrict__ cursor, int* __restrict__ csr) {
    int i = blockIdx.x * blockDim.x + threadIdx.x;
    if (i >= E_TOT) return;
    const int* ei; int base, E;
    if (i < E_WR)                    { ei = e_wr; base = B_WR; E = E_WR; }
    else if ((i -= E_WR) < E_CI)     { ei = e_ci; base = B_CI; E = E_CI; }
    else if ((i -= E_CI) < E_RH)     { ei = e_rh; base = B_RH; E = E_RH; }
    else if ((i -= E_RH) < E_RW)     { ei = e_rw; base = B_RW; E = E_RW; }
    else       { i -= E_RW;            ei = e_ht; base = B_HT; E = E_HT; }
    int s = __ldg(&ei[i]);
    int d = __ldg(&ei[E + i]);
    int pos = atomicAdd(&cursor[base + d], 1);
    csr[pos] = s;
}

__global__ void scan1_kernel(const int* __restrict__ cnt, int* __restrict__ rp,
                             int* __restrict__ partials) {
    __shared__ int s[256];
    int t = threadIdx.x, b = blockIdx.x;
    int i0 = b * 1024 + t * 4;
    int c0 = (i0     < NTOT) ? cnt[i0]     : 0;
    int c1 = (i0 + 1 < NTOT) ? cnt[i0 + 1] : 0;
    int c2 = (i0 + 2 < NTOT) ? cnt[i0 + 2] : 0;
    int c3 = (i0 + 3 < NTOT) ? cnt[i0 + 3] : 0;
    int ts = c0 + c1 + c2 + c3;
    s[t] = ts;
    __syncthreads();
    for (int off = 1; off < 256; off <<= 1) {
        int v = (t >= off) ? s[t - off] : 0;
        __syncthreads();
        s[t] += v;
        __syncthreads();
    }
    int p = s[t] - ts;
    if (t == 255) partials[b] = s[255];
    if (i0     < NTOT) rp[i0]     = p; p += c0;
    if (i0 + 1 < NTOT) rp[i0 + 1] = p; p += c1;
    if (i0 + 2 < NTOT) rp[i0 + 2] = p; p += c2;
    if (i0 + 3 < NTOT) rp[i0 + 3] = p;
}

__global__ void scan2_kernel(int* __restrict__ partials, int nblk) {
    __shared__ int s[512];
    int t = threadIdx.x;
    int v0 = (t < nblk) ? partials[t] : 0;
    s[t] = v0;
    __syncthreads();
    for (int off = 1; off < 512; off <<= 1) {
        int v = (t >= off) ? s[t - off] : 0;
        __syncthreads();
        s[t] += v;
        __syncthreads();
    }
    if (t < nblk) partials[t] = s[t] - v0;
}

__global__ void scan3_kernel(int* __restrict__ rp, const int* __restrict__ partials,
                             int* __restrict__ cursor) {
    int i = blockIdx.x * blockDim.x + threadIdx.x;
    if (i < NTOT) {
        int v = rp[i] + partials[i >> 10];
        rp[i] = v;
        cursor[i] = v;
    }
    if (i == 0) rp[NTOT] = E_TOT;
}

// ---------------- CSR aggregation: warp per dst, 4 edges in flight ----------------
// Lane layout: g = lane>>3 (edge slot 0..3), l8 = lane&7 (uint4 = 8 halves of the row).
// Per-segment mean scale applied pre-reduction; one shfl-reduction per destination.

__device__ __forceinline__ void gather_seg(const uint4* __restrict__ feat,
                                           const int* __restrict__ csr,
                                           int s, int e, int g, int l8,
                                           float* __restrict__ tot) {
    float acc[8] = {};
    #pragma unroll 2
    for (int i = s + g; i < e; i += 4) {
        int sv = __ldg(&csr[i]);
        uint4 v = __ldg(&feat[sv * 8 + l8]);
        float2 t0 = __half22float2(*reinterpret_cast<__half2*>(&v.x));
        float2 t1 = __half22float2(*reinterpret_cast<__half2*>(&v.y));
        float2 t2 = __half22float2(*reinterpret_cast<__half2*>(&v.z));
        float2 t3 = __half22float2(*reinterpret_cast<__half2*>(&v.w));
        acc[0] += t0.x; acc[1] += t0.y;
        acc[2] += t1.x; acc[3] += t1.y;
        acc[4] += t2.x; acc[5] += t2.y;
        acc[6] += t3.x; acc[7] += t3.y;
    }
    float r = (e > s) ? 1.0f / (float)(e - s) : 0.f;
    #pragma unroll
    for (int k = 0; k < 8; k++) tot[k] += acc[k] * r;
}

__device__ __forceinline__ void warp_reduce8(float* __restrict__ tot) {
    #pragma unroll
    for (int k = 0; k < 8; k++) {
        tot[k] += __shfl_xor_sync(0xffffffffu, tot[k], 8);
        tot[k] += __shfl_xor_sync(0xffffffffu, tot[k], 16);
    }
}

__device__ __forceinline__ uint4 pack8(const float* __restrict__ t) {
    __half2 h0 = __floats2half2_rn(t[0], t[1]);
    __half2 h1 = __floats2half2_rn(t[2], t[3]);
    __half2 h2 = __floats2half2_rn(t[4], t[5]);
    __half2 h3 = __floats2half2_rn(t[6], t[7]);
    uint4 o;
    o.x = *reinterpret_cast<unsigned*>(&h0);
    o.y = *reinterpret_cast<unsigned*>(&h1);
    o.z = *reinterpret_cast<unsigned*>(&h2);
    o.w = *reinterpret_cast<unsigned*>(&h3);
    return o;
}

// layer-1 for ALL node types in one launch: y = relu(y_self + sum_t mean_t)
__global__ void agg_l1_all(const uint4* __restrict__ hwr, const uint4* __restrict__ hci,
                           const uint4* __restrict__ hrh, const uint4* __restrict__ hrw,
                           const uint4* __restrict__ hht,
                           const int* __restrict__ csr, const int* __restrict__ rp,
                           uint4* __restrict__ p, uint4* __restrict__ a,
                           uint4* __restrict__ f) {
    int gw = (blockIdx.x * blockDim.x + threadIdx.x) >> 5;
    int lane = threadIdx.x & 31;
    int g = lane >> 3, l8 = lane & 7;
    if (gw >= N_PAPER + N_AUTHOR + N_FIELD) return;

    float tot[8] = {};
    uint4* y;
    int node;
    if (gw < N_PAPER) {
        node = gw;
        gather_seg(hwr, csr, __ldg(&rp[B_WR + node]), __ldg(&rp[B_WR + node + 1]), g, l8, tot);
        gather_seg(hci, csr, __ldg(&rp[B_CI + node]), __ldg(&rp[B_CI + node + 1]), g, l8, tot);
        gather_seg(hrh, csr, __ldg(&rp[B_RH + node]), __ldg(&rp[B_RH + node + 1]), g, l8, tot);
        y = p;
    } else if (gw < N_PAPER + N_AUTHOR) {
        node = gw - N_PAPER;
        gather_seg(hrw, csr, __ldg(&rp[B_RW + node]), __ldg(&rp[B_RW + node + 1]), g, l8, tot);
        y = a;
    } else {
        node = gw - N_PAPER - N_AUTHOR;
        gather_seg(hht, csr, __ldg(&rp[B_HT + node]), __ldg(&rp[B_HT + node + 1]), g, l8, tot);
        y = f;
    }
    warp_reduce8(tot);
    if (g == 0) {
        uint4 sv = y[node * 8 + l8];
        float2 s0 = __half22float2(*reinterpret_cast<__half2*>(&sv.x));
        float2 s1 = __half22float2(*reinterpret_cast<__half2*>(&sv.y));
        float2 s2 = __half22float2(*reinterpret_cast<__half2*>(&sv.z));
        float2 s3 = __half22float2(*reinterpret_cast<__half2*>(&sv.w));
        tot[0] = fmaxf(tot[0] + s0.x, 0.f); tot[1] = fmaxf(tot[1] + s0.y, 0.f);
        tot[2] = fmaxf(tot[2] + s1.x, 0.f); tot[3] = fmaxf(tot[3] + s1.y, 0.f);
        tot[4] = fmaxf(tot[4] + s2.x, 0.f); tot[5] = fmaxf(tot[5] + s2.y, 0.f);
        tot[6] = fmaxf(tot[6] + s3.x, 0.f); tot[7] = fmaxf(tot[7] + s3.y, 0.f);
        y[node * 8 + l8] = pack8(tot);
    }
}

// layer-2: all three paper means in one launch (plain mean, no self/relu)
__global__ void agg_mean3(const uint4* __restrict__ fa, const uint4* __restrict__ fp,
                          const uint4* __restrict__ ff,
                          const int* __restrict__ csr, const int* __restrict__ rp,
                          uint4* __restrict__ oa, uint4* __restrict__ op,
                          uint4* __restrict__ of) {
    int gw = (blockIdx.x * blockDim.x + threadIdx.x) >> 5;
    int lane = threadIdx.x & 31;
    int g = lane >> 3, l8 = lane & 7;
    if (gw >= 3 * N_PAPER) return;
    int t = gw / N_PAPER;
    int node = gw - t * N_PAPER;
    const uint4* feat = (t == 0) ? fa : (t == 1) ? fp : ff;
    uint4* o          = (t == 0) ? oa : (t == 1) ? op : of;
    int base = t * 100000;    // B_WR, B_CI, B_RH
    float tot[8] = {};
    gather_seg(feat, csr, __ldg(&rp[base + node]), __ldg(&rp[base + node + 1]), g, l8, tot);
    warp_reduce8(tot);
    if (g == 0) o[node * 8 + l8] = pack8(tot);
}

// ---------------- fp16 tensor-core GEMMs (m16n8k16, fp32 accum) ----------------

__device__ __forceinline__ void mma16(float* c, const unsigned* a, const unsigned* b) {
    asm volatile("mma.sync.aligned.m16n8k16.row.col.f32.f16.f16.f32 "
        "{%0,%1,%2,%3}, {%4,%5,%6,%7}, {%8,%9}, {%0,%1,%2,%3};"
        : "+f"(c[0]), "+f"(c[1]), "+f"(c[2]), "+f"(c[3])
        : "r"(a[0]), "r"(a[1]), "r"(a[2]), "r"(a[3]), "r"(b[0]), "r"(b[1]));
}

#define AST 36   // A: 128 rows x 32 half2 (K-chunk 64) + pad; conflict-free
#define WST 36   // W: 64 n-rows x 32 half2 + pad

// Multi-output projection GEMM: C_j[M x 64] = A[M x 128] @ Wcat[:, j*64:(j+1)*64] (+ bias_j)
__global__ __launch_bounds__(256) void gemm_proj_multi(
    const float* __restrict__ A, const float* __restrict__ W, int ldw,
    __half* o0, __half* o1, __half* o2, __half* o3,
    const float* b0, const float* b1, const float* b2, const float* b3, int M)
{
    __shared__ unsigned As[128][AST];
    __shared__ unsigned Ws[64][WST];
    const int tid = threadIdx.x;
    const int warp = tid >> 5, lane = tid & 31;
    const int gid = lane >> 2, tig = lane & 3;
    const int wm = (warp & 3) * 32;
    const int wn = (warp >> 2) * 32;
    const int row0 = blockIdx.y * 128;
    const int wc0 = blockIdx.x * 64;

    __half* C;
    const float* bias;
    switch (blockIdx.x) {
        case 0: C = o0; bias = b0; break;
        case 1: C = o1; bias = b1; break;
        case 2: C = o2; bias = b2; break;
        default: C = o3; bias = b3; break;
    }

    float acc[2][4][4] = {};

    #pragma unroll 1
    for (int kk = 0; kk < F_IN; kk += 64) {
        for (int i = tid; i < 128 * 16; i += 256) {
            int r = i >> 4, q = i & 15;
            int rg = row0 + r;
            float4 v = make_float4(0.f, 0.f, 0.f, 0.f);
            if (rg < M) v = *(const float4*)&A[rg * F_IN + kk + q * 4];
            __half2 h0 = __floats2half2_rn(v.x, v.y);
            __half2 h1 = __floats2half2_rn(v.z, v.w);
            As[r][q * 2]     = *(unsigned*)&h0;
            As[r][q * 2 + 1] = *(unsigned*)&h1;
        }
        for (int i = tid; i < 64 * 32; i += 256) {
            int n = i & 63, kp = i >> 6;
            float w0 = W[(kk + 2 * kp) * ldw + wc0 + n];
            float w1 = W[(kk + 2 * kp + 1) * ldw + wc0 + n];
            __half2 h = __floats2half2_rn(w0, w1);
            Ws[n][kp] = *(unsigned*)&h;
        }
        __syncthreads();
        #pragma unroll
        for (int kt = 0; kt < 4; kt++) {
            int k0h = kt * 8;
            unsigned a[2][4], b[4][2];
            #pragma unroll
            for (int mi = 0; mi < 2; mi++) {
                int r = wm + mi * 16 + gid;
                a[mi][0] = As[r][k0h + tig];
                a[mi][1] = As[r + 8][k0h + tig];
                a[mi][2] = As[r][k0h + tig + 4];
                a[mi][3] = As[r + 8][k0h + tig + 4];
            }
            #pragma unroll
            for (int ni = 0; ni < 4; ni++) {
                int n = wn + ni * 8 + gid;
                b[ni][0] = Ws[n][k0h + tig];
                b[ni][1] = Ws[n][k0h + tig + 4];
            }
            #pragma unroll
            for (int mi = 0; mi < 2; mi++)
                #pragma unroll
                for (int ni = 0; ni < 4; ni++)
                    mma16(acc[mi][ni], a[mi], b[ni]);
        }
        __syncthreads();
    }

    #pragma unroll
    for (int ni = 0; ni < 4; ni++) {
        int col = wn + ni * 8 + tig * 2;
        float2 bv = make_float2(0.f, 0.f);
        if (bias) bv = *(const float2*)&bias[col];
        #pragma unroll
        for (int mi = 0; mi < 2; mi++) {
            int r = row0 + wm + mi * 16 + gid;
            if (r < M)
                *(__half2*)&C[r * HID + col] =
                    __floats2half2_rn(acc[mi][ni][0] + bv.x, acc[mi][ni][1] + bv.y);
            if (r + 8 < M)
                *(__half2*)&C[(r + 8) * HID + col] =
                    __floats2half2_rn(acc[mi][ni][2] + bv.x, acc[mi][ni][3] + bv.y);
        }
    }
}

// C[M x 349] = sum_t A_t[M x 64] @ W_t[64 x 349] + bias
__global__ __launch_bounds__(256) void gemm_out_tc(
    const __half* __restrict__ A0, const __half* __restrict__ A1,
    const __half* __restrict__ A2, const __half* __restrict__ A3,
    const float* __restrict__ W0, const float* __restrict__ W1,
    const float* __restrict__ W2, const float* __restrict__ W3,
    const float* __restrict__ bias, float* __restrict__ C, int M)
{
    __shared__ unsigned As[128][AST];
    __shared__ unsigned Ws[64][WST];
    const int tid = threadIdx.x;
    const int warp = tid >> 5, lane = tid & 31;
    const int gid = lane >> 2, tig = lane & 3;
    const int wm = (warp & 3) * 32;
    const int wn = (warp >> 2) * 32;
    const int row0 = blockIdx.y * 128;
    const int col0 = blockIdx.x * 64;

    const __half* Aps[4] = {A0, A1, A2, A3};
    const float* Wps[4] = {W0, W1, W2, W3};

    float acc[2][4][4] = {};

    #pragma unroll 1
    for (int t = 0; t < 4; t++) {
        const __half* A = Aps[t];
        const float* W = Wps[t];
        for (int i = tid; i < 128 * 8; i += 256) {
            int r = i >> 3, q = i & 7;
            int rg = row0 + r;
            uint4 v = make_uint4(0u, 0u, 0u, 0u);
            if (rg < M) v = *(const uint4*)&A[rg * HID + q * 8];
            *(uint4*)&As[r][q * 4] = v;
        }
        for (int i = tid; i < 64 * 32; i += 256) {
            int n = i & 63, kp = i >> 6;
            int cg = col0 + n;
            float w0 = 0.f, w1 = 0.f;
            if (cg < OUTF) {
                w0 = W[(2 * kp) * OUTF + cg];
                w1 = W[(2 * kp + 1) * OUTF + cg];
            }
            __half2 h = __floats2half2_rn(w0, w1);
            Ws[n][kp] = *(unsigned*)&h;
        }
        __syncthreads();
        #pragma unroll
        for (int kt = 0; kt < 4; kt++) {
            int k0h = kt * 8;
            unsigned a[2][4], b[4][2];
            #pragma unroll
            for (int mi = 0; mi < 2; mi++) {
                int r = wm + mi * 16 + gid;
                a[mi][0] = As[r][k0h + tig];
                a[mi][1] = As[r + 8][k0h + tig];
                a[mi][2] = As[r][k0h + tig + 4];
                a[mi][3] = As[r + 8][k0h + tig + 4];
            }
            #pragma unroll
            for (int ni = 0; ni < 4; ni++) {
                int n = wn + ni * 8 + gid;
                b[ni][0] = Ws[n][k0h + tig];
                b[ni][1] = Ws[n][k0h + tig + 4];
            }
            #pragma unroll
            for (int mi = 0; mi < 2; mi++)
                #pragma unroll
                for (int ni = 0; ni < 4; ni++)
                    mma16(acc[mi][ni], a[mi], b[ni]);
        }
        __syncthreads();
    }

    #pragma unroll
    for (int ni = 0; ni < 4; ni++) {
        int col = col0 + wn + ni * 8 + tig * 2;
        float b0v = (col < OUTF) ? bias[col] : 0.f;
        float b1v = (col + 1 < OUTF) ? bias[col + 1] : 0.f;
        #pragma unroll
        for (int mi = 0; mi < 2; mi++) {
            int r = row0 + wm + mi * 16 + gid;
            if (r < M) {
                if (col < OUTF)     C[r * OUTF + col]     = acc[mi][ni][0] + b0v;
                if (col + 1 < OUTF) C[r * OUTF + col + 1] = acc[mi][ni][1] + b1v;
            }
            int r2 = r + 8;
            if (r2 < M) {
                if (col < OUTF)     C[r2 * OUTF + col]     = acc[mi][ni][2] + b0v;
                if (col + 1 < OUTF) C[r2 * OUTF + col + 1] = acc[mi][ni][3] + b1v;
            }
        }
    }
}

// ---------------- host launcher ----------------
extern "C" void kernel_launch(void* const* d_in, const int* in_sizes, int n_in,
                              void* d_out, int out_size) {
    (void)in_sizes; (void)n_in; (void)out_size;
    const float* x_paper  = (const float*)d_in[0];
    const float* x_author = (const float*)d_in[1];
    const float* x_field  = (const float*)d_in[2];
    const int* ei_wr = (const int*)d_in[3];
    const int* ei_rw = (const int*)d_in[4];
    const int* ei_ci = (const int*)d_in[5];
    const int* ei_ht = (const int*)d_in[6];
    const int* ei_rh = (const int*)d_in[7];
    const float* wl1_wr = (const float*)d_in[8];
    const float* wr1_wr = (const float*)d_in[9];
    const float* b1_wr  = (const float*)d_in[10];
    const float* wl1_rw = (const float*)d_in[11];
    const float* wr1_rw = (const float*)d_in[12];
    const float* b1_rw  = (const float*)d_in[13];
    const float* wl1_ci = (const float*)d_in[14];
    const float* wr1_ci = (const float*)d_in[15];
    const float* b1_ci  = (const float*)d_in[16];
    const float* wl1_ht = (const float*)d_in[17];
    const float* wr1_ht = (const float*)d_in[18];
    const float* b1_ht  = (const float*)d_in[19];
    const float* wl1_rh = (const float*)d_in[20];
    const float* wr1_rh = (const float*)d_in[21];
    const float* b1_rh  = (const float*)d_in[22];
    const float* wl2_wr = (const float*)d_in[23];
    const float* wr2_wr = (const float*)d_in[24];
    const float* b2_wr  = (const float*)d_in[25];
    const float* wl2_ci = (const float*)d_in[26];
    const float* wr2_ci = (const float*)d_in[27];
    const float* b2_ci  = (const float*)d_in[28];
    const float* wl2_rh = (const float*)d_in[29];
    const float* wr2_rh = (const float*)d_in[30];
    const float* b2_rh  = (const float*)d_in[31];
    float* out = (float*)d_out;

    __half *h_wr, *h_rw, *h_ci, *h_ht, *h_rh, *p1, *a1, *f1;
    __half *acc2_wr, *acc2_ci, *acc2_rh;
    float *bsum1p, *wsum2, *bsum2;
    float *wcat_p, *wcat_a, *wcat_f;
    int *cnt, *rowptr, *cursor, *partials, *csr;
    cudaGetSymbolAddress((void**)&h_wr, g_h_wr);
    cudaGetSymbolAddress((void**)&h_rw, g_h_rw);
    cudaGetSymbolAddress((void**)&h_ci, g_h_ci);
    cudaGetSymbolAddress((void**)&h_ht, g_h_ht);
    cudaGetSymbolAddress((void**)&h_rh, g_h_rh);
    cudaGetSymbolAddress((void**)&p1, g_p1);
    cudaGetSymbolAddress((void**)&a1, g_a1);
    cudaGetSymbolAddress((void**)&f1, g_f1);
    cudaGetSymbolAddress((void**)&acc2_wr, g_acc2_wr);
    cudaGetSymbolAddress((void**)&acc2_ci, g_acc2_ci);
    cudaGetSymbolAddress((void**)&acc2_rh, g_acc2_rh);
    cudaGetSymbolAddress((void**)&bsum1p, g_bsum1p);
    cudaGetSymbolAddress((void**)&wsum2, g_wsum2);
    cudaGetSymbolAddress((void**)&bsum2, g_bsum2);
    cudaGetSymbolAddress((void**)&wcat_p, g_wcat_p);
    cudaGetSymbolAddress((void**)&wcat_a, g_wcat_a);
    cudaGetSymbolAddress((void**)&wcat_f, g_wcat_f);
    cudaGetSymbolAddress((void**)&cnt, g_cnt);
    cudaGetSymbolAddress((void**)&rowptr, g_rowptr);
    cudaGetSymbolAddress((void**)&cursor, g_cursor);
    cudaGetSymbolAddress((void**)&partials, g_partials);
    cudaGetSymbolAddress((void**)&csr, g_csr);

    const int TPB = 256;
    const int SCAN_NBLK = (NTOT + 1023) / 1024;   // 440

    // ---- fused prep: all weight sums + concatenation (1 launch) ----
    prep_kernel<<<(PREP_TOT + TPB - 1) / TPB, TPB>>>(
        wr2_wr, wr2_ci, wr2_rh, b2_wr, b2_ci, b2_rh,
        b1_wr, b1_ci, b1_rh,
        wl1_rw, wl1_ci, wl1_ht,
        wr1_wr, wr1_ci, wr1_rh,
        wl1_wr, wr1_rw, wl1_rh, wr1_ht,
        wsum2, bsum2, bsum1p, wcat_p, wcat_a, wcat_f);

    // ---- fused layer-1 projections (3 launches) ----
    {
        dim3 gp(4, (N_PAPER + 127) / 128);
        gemm_proj_multi<<<gp, TPB>>>(x_paper, wcat_p, 256,
                                     h_rw, h_ci, h_ht, p1,
                                     nullptr, nullptr, nullptr, bsum1p, N_PAPER);
        dim3 ga(2, (N_AUTHOR + 127) / 128);
        gemm_proj_multi<<<ga, TPB>>>(x_author, wcat_a, 128,
                                     h_wr, a1, nullptr, nullptr,
                                     nullptr, b1_rw, nullptr, nullptr, N_AUTHOR);
        dim3 gf(2, (N_FIELD + 127) / 128);
        gemm_proj_multi<<<gf, TPB>>>(x_field, wcat_f, 128,
                                     h_rh, f1, nullptr, nullptr,
                                     nullptr, b1_ht, nullptr, nullptr, N_FIELD);
    }

    // ---- CSR build ----
    zero_cnt_kernel<<<(NTOT / 4 + TPB - 1) / TPB, TPB>>>((int4*)cnt, NTOT / 4);
    count_all<<<(E_TOT + TPB - 1) / TPB, TPB>>>(ei_wr, ei_ci, ei_rh, ei_rw, ei_ht, cnt);
    scan1_kernel<<<SCAN_NBLK, 256>>>(cnt, rowptr, partials);
    scan2_kernel<<<1, 512>>>(partials, SCAN_NBLK);
    scan3_kernel<<<(NTOT + TPB - 1) / TPB, TPB>>>(rowptr, partials, cursor);
    reorder_all<<<(E_TOT + TPB - 1) / TPB, TPB>>>(ei_wr, ei_ci, ei_rh, ei_rw, ei_ht,
                                                  cursor, csr);

    // ---- layer-1 aggregation: all node types, one launch ----
    {
        long long warps = (long long)(N_PAPER + N_AUTHOR + N_FIELD);
        int blocks = (int)((warps * 32 + TPB - 1) / TPB);
        agg_l1_all<<<blocks, TPB>>>(
            (const uint4*)h_wr, (const uint4*)h_ci, (const uint4*)h_rh,
            (const uint4*)h_rw, (const uint4*)h_ht,
            csr, rowptr, (uint4*)p1, (uint4*)a1, (uint4*)f1);
    }

    // ---- layer-2 aggregation: all three means, one launch ----
    {
        int blocks = (3 * N_PAPER * 32 + TPB - 1) / TPB;
        agg_mean3<<<blocks, TPB>>>(
            (const uint4*)a1, (const uint4*)p1, (const uint4*)f1,
            csr, rowptr,
            (uint4*)acc2_wr, (uint4*)acc2_ci, (uint4*)acc2_rh);
    }

    // ---- fused output GEMM ----
    {
        dim3 grid((OUTF + 63) / 64, (N_PAPER + 127) / 128);
        gemm_out_tc<<<grid, TPB>>>(acc2_wr, acc2_ci, acc2_rh, p1,
                                   wl2_wr, wl2_ci, wl2_rh, wsum2,
                                   bsum2, out, N_PAPER);
    }
}